// round 7
// baseline (speedup 1.0000x reference)
#include <cuda_runtime.h>
#include <cuda_fp16.h>
#include <cstdint>
#include <cstddef>

// ---------------- problem constants ----------------
#define M_TOK 8192
#define IN_F  4096
#define OUT_F 4096
#define RANK  32
#define GS    64
#define KP    4160          // IN_F + RANK (lora) + 32 (zero pad); multiple of 64
#define KT_MAIN (KP / 64)   // 65 K-tiles of 64

// ---------------- scratch (device globals; no runtime allocation) ----------------
__device__ __align__(128) __half g_A [(size_t)M_TOK * KP];   // A' = [xdq | lora_act | 0]
__device__ __align__(128) __half g_B [(size_t)OUT_F * KP];   // B' = [wdq | proj_up  | 0]
__device__ __align__(128) __half g_Xs[(size_t)M_TOK * IN_F]; // smoothed activations (half)
__device__ int g_qw_is_i32;                                  // qweight dtype flag

// =======================================================================
// Kernel 0: detect whether qweight buffer is int32 (harness-promoted) or int8.
// =======================================================================
__global__ void detect_qw_kernel(const int* __restrict__ qw) {
    if (threadIdx.x == 0 && blockIdx.x == 0) {
        int ok = 1;
        for (int i = 0; i < 64; ++i) {
            int v = qw[i];
            if (v < -8 || v > 7) { ok = 0; break; }
        }
        g_qw_is_i32 = ok;
    }
}

// =======================================================================
// Kernel 1: activation prep.
//  xs = x / smooth;  g_Xs = half(xs);
//  per-token per-64 group: ascale = max(max|xs|/7, 1e-8); q = clip(rint(xs/ascale),-8,7)
//  g_A[:, 0:4096] = half(q*ascale);  g_A[:, 4128:4160] = 0
// =======================================================================
__global__ void __launch_bounds__(256) prep_x_kernel(const float* __restrict__ x,
                                                     const float* __restrict__ smooth) {
    const int m = blockIdx.x;
    const int t = threadIdx.x;
    const int i0 = t * 16;

    float v[16];
    const float4* xp = (const float4*)(x + (size_t)m * IN_F + i0);
    const float4* sp = (const float4*)(smooth + i0);
#pragma unroll
    for (int j = 0; j < 4; ++j) {
        float4 xv = xp[j];
        float4 sv = sp[j];
        v[4*j+0] = xv.x / sv.x;
        v[4*j+1] = xv.y / sv.y;
        v[4*j+2] = xv.z / sv.z;
        v[4*j+3] = xv.w / sv.w;
    }

    __align__(16) __half hs[16];
#pragma unroll
    for (int j = 0; j < 16; ++j) hs[j] = __float2half_rn(v[j]);
    {
        uint4* dst = (uint4*)(g_Xs + (size_t)m * IN_F + i0);
        dst[0] = ((const uint4*)hs)[0];
        dst[1] = ((const uint4*)hs)[1];
    }

    float am = 0.f;
#pragma unroll
    for (int j = 0; j < 16; ++j) am = fmaxf(am, fabsf(v[j]));
    am = fmaxf(am, __shfl_xor_sync(0xffffffffu, am, 1));
    am = fmaxf(am, __shfl_xor_sync(0xffffffffu, am, 2));
    const float asc = fmaxf(am / 7.0f, 1e-8f);

    __align__(16) __half hq[16];
#pragma unroll
    for (int j = 0; j < 16; ++j) {
        float q = rintf(v[j] / asc);            // round-half-even == jnp.round
        q = fminf(fmaxf(q, -8.0f), 7.0f);
        hq[j] = __float2half_rn(q * asc);
    }
    {
        uint4* dst = (uint4*)(g_A + (size_t)m * KP + i0);
        dst[0] = ((const uint4*)hq)[0];
        dst[1] = ((const uint4*)hq)[1];
    }

    if (t < 4) {
        uint4 z = make_uint4(0u, 0u, 0u, 0u);
        *(uint4*)(g_A + (size_t)m * KP + (IN_F + RANK) + t * 8) = z;
    }
}

// =======================================================================
// Kernel 2: weight prep (handles qweight stored as int32 OR int8).
// =======================================================================
__global__ void __launch_bounds__(256) prep_w_kernel(const void* __restrict__ qw_raw,
                                                     const float* __restrict__ wsc,
                                                     const float* __restrict__ pu) {
    const int o = blockIdx.x;
    const int t = threadIdx.x;
    const int i0 = t * 16;                        // group (i0>>6) constant over 16 elems

    float qv[16];
    if (g_qw_is_i32) {
        const int4* qp = (const int4*)((const int*)qw_raw + (size_t)o * IN_F + i0);
#pragma unroll
        for (int j = 0; j < 4; ++j) {
            int4 w = qp[j];
            qv[4*j+0] = (float)w.x;
            qv[4*j+1] = (float)w.y;
            qv[4*j+2] = (float)w.z;
            qv[4*j+3] = (float)w.w;
        }
    } else {
        __align__(16) int8_t qb[16];
        *(uint4*)qb = *(const uint4*)((const int8_t*)qw_raw + (size_t)o * IN_F + i0);
#pragma unroll
        for (int j = 0; j < 16; ++j) qv[j] = (float)qb[j];
    }

    const float ws = wsc[(i0 >> 6) * OUT_F + o];
    __align__(16) __half h[16];
#pragma unroll
    for (int j = 0; j < 16; ++j) h[j] = __float2half_rn(qv[j] * ws);
    {
        uint4* dst = (uint4*)(g_B + (size_t)o * KP + i0);
        dst[0] = ((const uint4*)h)[0];
        dst[1] = ((const uint4*)h)[1];
    }

    if (t < RANK) {
        g_B[(size_t)o * KP + IN_F + t] = __float2half_rn(pu[(size_t)o * RANK + t]);
    } else if (t < RANK + 32) {
        g_B[(size_t)o * KP + IN_F + RANK + (t - RANK)] = __float2half_rn(0.0f);
    }
}

// =======================================================================
// Kernel 3: lora GEMM.  lora[m, r] = sum_i g_Xs[m,i] * proj_down[i,r]
// Writes half(lora) into g_A[:, 4096:4128].
// FIX (R6): Xs tile is 64x128 halfs = 1024 uint4 -> loader needs j<4 (was j<2,
// leaving rows 32..63 uninitialized -> rel_err 2.6e-2).
// =======================================================================
__global__ void __launch_bounds__(256) lora_kernel(const float* __restrict__ pd) {
    __shared__ __half Xs_s[64][128];
    __shared__ float  pd_s[128][RANK];

    const int t = threadIdx.x;
    const int m0 = blockIdx.x * 64;
    const int row = t >> 2;
    const int r0  = (t & 3) * 8;

    float acc[8];
#pragma unroll
    for (int j = 0; j < 8; ++j) acc[j] = 0.f;

    for (int kc = 0; kc < IN_F / 128; ++kc) {
        // load Xs tile: 64 rows x 16 uint4 = 1024 uint4
#pragma unroll
        for (int j = 0; j < 4; ++j) {
            int c = t + j * 256;
            int rr = c >> 4, cc = c & 15;
            *(uint4*)&Xs_s[rr][cc * 8] =
                *(const uint4*)(g_Xs + (size_t)(m0 + rr) * IN_F + kc * 128 + cc * 8);
        }
        // load proj_down chunk: 128 x 32 f32 = 1024 float4
#pragma unroll
        for (int j = 0; j < 4; ++j) {
            int c = t + j * 256;
            int rr = c >> 3, cc = c & 7;
            *(float4*)&pd_s[rr][cc * 4] =
                *(const float4*)(pd + (size_t)(kc * 128 + rr) * RANK + cc * 4);
        }
        __syncthreads();

#pragma unroll 4
        for (int kk = 0; kk < 128; ++kk) {
            float a = __half2float(Xs_s[row][kk]);
            float4 p0 = *(const float4*)&pd_s[kk][r0];
            float4 p1 = *(const float4*)&pd_s[kk][r0 + 4];
            acc[0] += a * p0.x;  acc[1] += a * p0.y;
            acc[2] += a * p0.z;  acc[3] += a * p0.w;
            acc[4] += a * p1.x;  acc[5] += a * p1.y;
            acc[6] += a * p1.z;  acc[7] += a * p1.w;
        }
        __syncthreads();
    }

    __align__(16) __half h[8];
#pragma unroll
    for (int j = 0; j < 8; ++j) h[j] = __float2half_rn(acc[j]);
    *(uint4*)(g_A + (size_t)(m0 + row) * KP + IN_F + r0) = *(const uint4*)h;
}

// =======================================================================
// Kernel 4: main GEMM.  out[m, n] = sum_k g_A[m,k] * g_B[n,k]   (f32 out)
// BM=BN=128, BK=64, 256 threads (8 warps), warp tile 64x32, 3-stage cp.async.
// =======================================================================
#define SA 72
#define STAGE_H (128 * SA)
#define SMEM_BYTES (3 * 2 * STAGE_H * 2)         // 110592 bytes

__device__ __forceinline__ void cp16(void* sdst, const void* gsrc) {
    unsigned sa = (unsigned)__cvta_generic_to_shared(sdst);
    asm volatile("cp.async.cg.shared.global [%0], [%1], 16;\n" :: "r"(sa), "l"(gsrc));
}

__device__ __forceinline__ void load_tile(const __half* __restrict__ gbase,
                                          __half* __restrict__ sdst, int t) {
#pragma unroll
    for (int j = 0; j < 4; ++j) {
        int c = t + j * 256;
        int row = c >> 3, cc = c & 7;
        cp16(sdst + row * SA + cc * 8, gbase + (size_t)row * KP + cc * 8);
    }
}

#define MMA_16816(C, A, B)                                                     \
    asm volatile("mma.sync.aligned.m16n8k16.row.col.f32.f16.f16.f32 "          \
                 "{%0,%1,%2,%3}, {%4,%5,%6,%7}, {%8,%9}, {%0,%1,%2,%3};\n"     \
                 : "+f"((C)[0]), "+f"((C)[1]), "+f"((C)[2]), "+f"((C)[3])      \
                 : "r"((A)[0]), "r"((A)[1]), "r"((A)[2]), "r"((A)[3]),         \
                   "r"((B)[0]), "r"((B)[1]))

__global__ void __launch_bounds__(256, 1) gemm_main_kernel(float* __restrict__ out) {
    extern __shared__ __half smem[];
    __half* As = smem;
    __half* Bs = smem + 3 * STAGE_H;

    const int t = threadIdx.x;
    const int wid = t >> 5, lane = t & 31;
    const int wm = wid & 1, wn = wid >> 1;
    const int gid = lane >> 2, tid4 = lane & 3;
    const int m0 = blockIdx.y * 128;
    const int n0 = blockIdx.x * 128;

    const __half* gA = g_A + (size_t)m0 * KP;
    const __half* gB = g_B + (size_t)n0 * KP;

    float c[4][4][4];
#pragma unroll
    for (int mi = 0; mi < 4; ++mi)
#pragma unroll
        for (int ni = 0; ni < 4; ++ni)
#pragma unroll
            for (int j = 0; j < 4; ++j) c[mi][ni][j] = 0.f;

    load_tile(gA, As, t);
    load_tile(gB, Bs, t);
    asm volatile("cp.async.commit_group;\n");
    load_tile(gA + 64, As + STAGE_H, t);
    load_tile(gB + 64, Bs + STAGE_H, t);
    asm volatile("cp.async.commit_group;\n");

    int s = 0;
    for (int kt = 0; kt < KT_MAIN; ++kt) {
        asm volatile("cp.async.wait_group 1;\n");
        __syncthreads();

        if (kt + 2 < KT_MAIN) {
            int s2 = kt + 2;
            s2 = s2 - (s2 / 3) * 3;
            load_tile(gA + (size_t)(kt + 2) * 64, As + s2 * STAGE_H, t);
            load_tile(gB + (size_t)(kt + 2) * 64, Bs + s2 * STAGE_H, t);
        }
        asm volatile("cp.async.commit_group;\n");

        const __half* As_ = As + s * STAGE_H;
        const __half* Bs_ = Bs + s * STAGE_H;
#pragma unroll
        for (int ks = 0; ks < 4; ++ks) {
            uint32_t af[4][4], bf[4][2];
#pragma unroll
            for (int mi = 0; mi < 4; ++mi) {
                const __half* p = As_ + (wm * 64 + mi * 16 + gid) * SA + ks * 16 + tid4 * 2;
                af[mi][0] = *(const uint32_t*)(p);
                af[mi][1] = *(const uint32_t*)(p + 8 * SA);
                af[mi][2] = *(const uint32_t*)(p + 8);
                af[mi][3] = *(const uint32_t*)(p + 8 * SA + 8);
            }
#pragma unroll
            for (int ni = 0; ni < 4; ++ni) {
                const __half* q = Bs_ + (wn * 32 + ni * 8 + gid) * SA + ks * 16 + tid4 * 2;
                bf[ni][0] = *(const uint32_t*)(q);
                bf[ni][1] = *(const uint32_t*)(q + 8);
            }
#pragma unroll
            for (int mi = 0; mi < 4; ++mi)
#pragma unroll
                for (int ni = 0; ni < 4; ++ni)
                    MMA_16816(c[mi][ni], af[mi], bf[ni]);
        }
        ++s;
        if (s == 3) s = 0;
    }

#pragma unroll
    for (int mi = 0; mi < 4; ++mi) {
#pragma unroll
        for (int ni = 0; ni < 4; ++ni) {
            int row = m0 + wm * 64 + mi * 16 + gid;
            int col = n0 + wn * 32 + ni * 8 + tid4 * 2;
            float2 v0 = make_float2(c[mi][ni][0], c[mi][ni][1]);
            float2 v1 = make_float2(c[mi][ni][2], c[mi][ni][3]);
            *(float2*)(out + (size_t)row * OUT_F + col) = v0;
            *(float2*)(out + (size_t)(row + 8) * OUT_F + col) = v1;
        }
    }
}

// =======================================================================
// launch: remap inputs by element count, positional fallback to metadata order.
// =======================================================================
extern "C" void kernel_launch(void* const* d_in, const int* in_sizes, int n_in,
                              void* d_out, int out_size) {
    const void* x   = nullptr;
    const void* qw  = nullptr;
    const void* wsc = nullptr;
    const void* smo = nullptr;
    const void* pd  = nullptr;
    const void* pu  = nullptr;

    for (int i = 0; i < n_in; ++i) {
        switch (in_sizes[i]) {
            case 33554432: x   = d_in[i]; break;
            case 16777216: qw  = d_in[i]; break;
            case 262144:   wsc = d_in[i]; break;
            case 4096:     smo = d_in[i]; break;
            case 131072:   if (!pd) pd = d_in[i]; else pu = d_in[i]; break;
            default: break;
        }
    }
    if (!x || !qw || !wsc || !smo || !pd || !pu) {
        x   = d_in[0];
        qw  = d_in[1];
        wsc = d_in[2];
        smo = d_in[3];
        pd  = d_in[4];
        pu  = d_in[5];
    }

    float* out = (float*)d_out;

    cudaFuncSetAttribute(gemm_main_kernel,
                         cudaFuncAttributeMaxDynamicSharedMemorySize, SMEM_BYTES);

    detect_qw_kernel<<<1, 32>>>((const int*)qw);
    prep_x_kernel<<<M_TOK, 256>>>((const float*)x, (const float*)smo);
    prep_w_kernel<<<OUT_F, 256>>>(qw, (const float*)wsc, (const float*)pu);
    lora_kernel<<<M_TOK / 64, 256>>>((const float*)pd);
    gemm_main_kernel<<<dim3(OUT_F / 128, M_TOK / 128), 256, SMEM_BYTES>>>(out);
}

// round 10
// speedup vs baseline: 1.1696x; 1.1696x over previous
#include <cuda_runtime.h>
#include <cuda_fp16.h>
#include <cstdint>
#include <cstddef>

// ---------------- problem constants ----------------
#define M_TOK 8192
#define IN_F  4096
#define OUT_F 4096
#define RANK  32
#define GS    64
#define KP    4160          // IN_F + RANK (lora) + 32 (zero pad); multiple of 64
#define KT_MAIN (KP / 64)   // 65 K-tiles of 64

// ---------------- scratch (device globals; no runtime allocation) ----------------
__device__ __align__(128) __half g_A [(size_t)M_TOK * KP];   // A' = [xdq | lora_act | 0]
__device__ __align__(128) __half g_B [(size_t)OUT_F * KP];   // B' = [wdq | proj_up  | 0]
__device__ __align__(128) __half g_Xs[(size_t)M_TOK * IN_F]; // smoothed activations (half)
__device__ __align__(128) float  g_lacc[4][M_TOK][RANK];     // split-K lora partials
__device__ int g_qw_is_i32;                                  // qweight dtype flag

// =======================================================================
// Kernel 0: qweight dtype detect (int32-promoted vs raw int8)
// =======================================================================
__global__ void detect_qw_kernel(const int* __restrict__ qw) {
    if (threadIdx.x == 0 && blockIdx.x == 0) {
        int ok = 1;
        for (int i = 0; i < 64; ++i) {
            int v = qw[i];
            if (v < -8 || v > 7) { ok = 0; break; }
        }
        g_qw_is_i32 = ok;
    }
}

// =======================================================================
// Kernel 1: activation prep (smooth, quantize-dequantize, store A' cols 0..4095)
// =======================================================================
__global__ void __launch_bounds__(256) prep_x_kernel(const float* __restrict__ x,
                                                     const float* __restrict__ smooth) {
    const int m = blockIdx.x;
    const int t = threadIdx.x;
    const int i0 = t * 16;

    float v[16];
    const float4* xp = (const float4*)(x + (size_t)m * IN_F + i0);
    const float4* sp = (const float4*)(smooth + i0);
#pragma unroll
    for (int j = 0; j < 4; ++j) {
        float4 xv = xp[j];
        float4 sv = sp[j];
        v[4*j+0] = xv.x / sv.x;
        v[4*j+1] = xv.y / sv.y;
        v[4*j+2] = xv.z / sv.z;
        v[4*j+3] = xv.w / sv.w;
    }

    __align__(16) __half hs[16];
#pragma unroll
    for (int j = 0; j < 16; ++j) hs[j] = __float2half_rn(v[j]);
    {
        uint4* dst = (uint4*)(g_Xs + (size_t)m * IN_F + i0);
        dst[0] = ((const uint4*)hs)[0];
        dst[1] = ((const uint4*)hs)[1];
    }

    float am = 0.f;
#pragma unroll
    for (int j = 0; j < 16; ++j) am = fmaxf(am, fabsf(v[j]));
    am = fmaxf(am, __shfl_xor_sync(0xffffffffu, am, 1));
    am = fmaxf(am, __shfl_xor_sync(0xffffffffu, am, 2));
    const float asc = fmaxf(am / 7.0f, 1e-8f);

    __align__(16) __half hq[16];
#pragma unroll
    for (int j = 0; j < 16; ++j) {
        float q = rintf(v[j] / asc);            // round-half-even == jnp.round
        q = fminf(fmaxf(q, -8.0f), 7.0f);
        hq[j] = __float2half_rn(q * asc);
    }
    {
        uint4* dst = (uint4*)(g_A + (size_t)m * KP + i0);
        dst[0] = ((const uint4*)hq)[0];
        dst[1] = ((const uint4*)hq)[1];
    }

    if (t < 4) {
        uint4 z = make_uint4(0u, 0u, 0u, 0u);
        *(uint4*)(g_A + (size_t)m * KP + (IN_F + RANK) + t * 8) = z;
    }
}

// =======================================================================
// Kernel 2: weight prep (int32 or int8 qweight)
// =======================================================================
__global__ void __launch_bounds__(256) prep_w_kernel(const void* __restrict__ qw_raw,
                                                     const float* __restrict__ wsc,
                                                     const float* __restrict__ pu) {
    const int o = blockIdx.x;
    const int t = threadIdx.x;
    const int i0 = t * 16;

    float qv[16];
    if (g_qw_is_i32) {
        const int4* qp = (const int4*)((const int*)qw_raw + (size_t)o * IN_F + i0);
#pragma unroll
        for (int j = 0; j < 4; ++j) {
            int4 w = qp[j];
            qv[4*j+0] = (float)w.x;
            qv[4*j+1] = (float)w.y;
            qv[4*j+2] = (float)w.z;
            qv[4*j+3] = (float)w.w;
        }
    } else {
        __align__(16) int8_t qb[16];
        *(uint4*)qb = *(const uint4*)((const int8_t*)qw_raw + (size_t)o * IN_F + i0);
#pragma unroll
        for (int j = 0; j < 16; ++j) qv[j] = (float)qb[j];
    }

    const float ws = wsc[(i0 >> 6) * OUT_F + o];
    __align__(16) __half h[16];
#pragma unroll
    for (int j = 0; j < 16; ++j) h[j] = __float2half_rn(qv[j] * ws);
    {
        uint4* dst = (uint4*)(g_B + (size_t)o * KP + i0);
        dst[0] = ((const uint4*)h)[0];
        dst[1] = ((const uint4*)h)[1];
    }

    if (t < RANK) {
        g_B[(size_t)o * KP + IN_F + t] = __float2half_rn(pu[(size_t)o * RANK + t]);
    } else if (t < RANK + 32) {
        g_B[(size_t)o * KP + IN_F + RANK + (t - RANK)] = __float2half_rn(0.0f);
    }
}

// =======================================================================
// Kernel 3a: split-K lora partials. grid (M/64, 4). Deterministic f32 partials.
// =======================================================================
__global__ void __launch_bounds__(256) lora_part_kernel(const float* __restrict__ pd) {
    __shared__ __half Xs_s[64][128];
    __shared__ float  pd_s[128][RANK];

    const int t = threadIdx.x;
    const int m0 = blockIdx.x * 64;
    const int kb = blockIdx.y;               // 0..3
    const int row = t >> 2;
    const int r0  = (t & 3) * 8;

    float acc[8];
#pragma unroll
    for (int j = 0; j < 8; ++j) acc[j] = 0.f;

    for (int kc = kb * 8; kc < kb * 8 + 8; ++kc) {   // 8 chunks of 128
#pragma unroll
        for (int j = 0; j < 4; ++j) {
            int c = t + j * 256;
            int rr = c >> 4, cc = c & 15;
            *(uint4*)&Xs_s[rr][cc * 8] =
                *(const uint4*)(g_Xs + (size_t)(m0 + rr) * IN_F + kc * 128 + cc * 8);
        }
#pragma unroll
        for (int j = 0; j < 4; ++j) {
            int c = t + j * 256;
            int rr = c >> 3, cc = c & 7;
            *(float4*)&pd_s[rr][cc * 4] =
                *(const float4*)(pd + (size_t)(kc * 128 + rr) * RANK + cc * 4);
        }
        __syncthreads();

#pragma unroll 4
        for (int kk = 0; kk < 128; ++kk) {
            float a = __half2float(Xs_s[row][kk]);
            float4 p0 = *(const float4*)&pd_s[kk][r0];
            float4 p1 = *(const float4*)&pd_s[kk][r0 + 4];
            acc[0] += a * p0.x;  acc[1] += a * p0.y;
            acc[2] += a * p0.z;  acc[3] += a * p0.w;
            acc[4] += a * p1.x;  acc[5] += a * p1.y;
            acc[6] += a * p1.z;  acc[7] += a * p1.w;
        }
        __syncthreads();
    }

    *(float4*)&g_lacc[kb][m0 + row][r0]     = make_float4(acc[0], acc[1], acc[2], acc[3]);
    *(float4*)&g_lacc[kb][m0 + row][r0 + 4] = make_float4(acc[4], acc[5], acc[6], acc[7]);
}

// Kernel 3b: pack lora partial sums into g_A cols 4096..4127 (half)
__global__ void __launch_bounds__(256) lora_pack_kernel() {
    int idx = blockIdx.x * 256 + threadIdx.x;     // 0 .. M*RANK-1
    int m = idx >> 5, r = idx & 31;
    float s = g_lacc[0][m][r] + g_lacc[1][m][r] + g_lacc[2][m][r] + g_lacc[3][m][r];
    g_A[(size_t)m * KP + IN_F + r] = __float2half_rn(s);
}

// =======================================================================
// Kernel 4: main GEMM, mma.sync + ldmatrix.
// BM=256, BN=128, BK=64. 256 threads = 8 warps (wm 0..3, wn 0..1),
// warp tile 64x64 -> 4x8 m16n8k16 frags. 3-stage cp.async. SA=72 stride.
// =======================================================================
#define SA 72
#define A_ROWS 256
#define B_ROWS 128
#define STAGE_H ((A_ROWS + B_ROWS) * SA)          // halfs per stage
#define B_OFF_H (A_ROWS * SA)
#define SMEM_BYTES (3 * STAGE_H * 2)              // 165888 bytes

__device__ __forceinline__ uint32_t smem_u32(const void* p) {
    uint32_t a;
    asm("{ .reg .u64 t; cvta.to.shared.u64 t, %1; cvt.u32.u64 %0, t; }" : "=r"(a) : "l"(p));
    return a;
}
__device__ __forceinline__ void cp16s(uint32_t sdst, const void* gsrc) {
    asm volatile("cp.async.cg.shared.global [%0], [%1], 16;\n" :: "r"(sdst), "l"(gsrc));
}
#define LDSM_X4(r0, r1, r2, r3, a)                                             \
    asm volatile("ldmatrix.sync.aligned.m8n8.x4.shared.b16 {%0,%1,%2,%3}, [%4];" \
                 : "=r"(r0), "=r"(r1), "=r"(r2), "=r"(r3) : "r"(a))
#define MMA_16816(C, A0, A1, A2, A3, B0, B1)                                   \
    asm volatile("mma.sync.aligned.m16n8k16.row.col.f32.f16.f16.f32 "          \
                 "{%0,%1,%2,%3}, {%4,%5,%6,%7}, {%8,%9}, {%0,%1,%2,%3};\n"     \
                 : "+f"((C)[0]), "+f"((C)[1]), "+f"((C)[2]), "+f"((C)[3])      \
                 : "r"(A0), "r"(A1), "r"(A2), "r"(A3), "r"(B0), "r"(B1))

__device__ __forceinline__ void load_stage(uint32_t sbase, int slot, int kt,
                                           int m0, int n0, int t) {
    uint32_t st = sbase + slot * (STAGE_H * 2);
    const __half* gA = g_A + (size_t)m0 * KP + kt * 64;
    const __half* gB = g_B + (size_t)n0 * KP + kt * 64;
#pragma unroll
    for (int j = 0; j < 12; ++j) {                // 384 rows x 8 chunks / 256 thr
        int c = j * 256 + t;
        int row = c >> 3, cc = c & 7;
        if (row < A_ROWS) {
            cp16s(st + (row * SA + cc * 8) * 2, gA + (size_t)row * KP + cc * 8);
        } else {
            int br = row - A_ROWS;
            cp16s(st + (B_OFF_H + br * SA + cc * 8) * 2, gB + (size_t)br * KP + cc * 8);
        }
    }
}

__global__ void __launch_bounds__(256, 1) gemm_main_kernel(float* __restrict__ out) {
    extern __shared__ __align__(128) __half smem[];
    uint32_t sbase = smem_u32(smem);

    const int t = threadIdx.x;
    const int wid = t >> 5, lane = t & 31;
    const int wm = wid >> 1, wn = wid & 1;        // 4 x 2 warp grid
    const int gid = lane >> 2, tid4 = lane & 3;
    const int n0 = blockIdx.x * B_ROWS;
    const int m0 = blockIdx.y * A_ROWS;

    // ldmatrix per-lane row/col offsets (in halfs, within stage)
    const int a_r = (lane & 15);                  // row within 16
    const int a_k = (lane >> 4) * 8;              // k-half select
    const int b_r = ((lane >> 4) << 3) + (lane & 7);  // n within 16
    const int b_k = ((lane >> 3) & 1) * 8;

    float c[4][8][4];
#pragma unroll
    for (int mi = 0; mi < 4; ++mi)
#pragma unroll
        for (int ni = 0; ni < 8; ++ni)
#pragma unroll
            for (int j = 0; j < 4; ++j) c[mi][ni][j] = 0.f;

    load_stage(sbase, 0, 0, m0, n0, t);
    asm volatile("cp.async.commit_group;\n");
    load_stage(sbase, 1, 1, m0, n0, t);
    asm volatile("cp.async.commit_group;\n");

    int s = 0;
    for (int kt = 0; kt < KT_MAIN; ++kt) {
        asm volatile("cp.async.wait_group 1;\n");
        __syncthreads();

        if (kt + 2 < KT_MAIN) {
            int s2 = kt + 2;
            s2 -= (s2 / 3) * 3;
            load_stage(sbase, s2, kt + 2, m0, n0, t);
        }
        asm volatile("cp.async.commit_group;\n");

        uint32_t aS = sbase + s * (STAGE_H * 2);
        uint32_t bS = aS + B_OFF_H * 2;
#pragma unroll
        for (int ks = 0; ks < 4; ++ks) {
            uint32_t af[4][4], bf[8][2];
#pragma unroll
            for (int mi = 0; mi < 4; ++mi) {
                uint32_t addr = aS + ((wm * 64 + mi * 16 + a_r) * SA + ks * 16 + a_k) * 2;
                LDSM_X4(af[mi][0], af[mi][1], af[mi][2], af[mi][3], addr);
            }
#pragma unroll
            for (int np = 0; np < 4; ++np) {      // pairs of n8 frags
                uint32_t addr = bS + ((wn * 64 + np * 16 + b_r) * SA + ks * 16 + b_k) * 2;
                LDSM_X4(bf[2*np][0], bf[2*np][1], bf[2*np+1][0], bf[2*np+1][1], addr);
            }
#pragma unroll
            for (int mi = 0; mi < 4; ++mi)
#pragma unroll
                for (int ni = 0; ni < 8; ++ni)
                    MMA_16816(c[mi][ni], af[mi][0], af[mi][1], af[mi][2], af[mi][3],
                              bf[ni][0], bf[ni][1]);
        }
        ++s;
        if (s == 3) s = 0;
    }

    // epilogue: f32 stores
#pragma unroll
    for (int mi = 0; mi < 4; ++mi) {
#pragma unroll
        for (int ni = 0; ni < 8; ++ni) {
            int row = m0 + wm * 64 + mi * 16 + gid;
            int col = n0 + wn * 64 + ni * 8 + tid4 * 2;
            *(float2*)(out + (size_t)row * OUT_F + col) =
                make_float2(c[mi][ni][0], c[mi][ni][1]);
            *(float2*)(out + (size_t)(row + 8) * OUT_F + col) =
                make_float2(c[mi][ni][2], c[mi][ni][3]);
        }
    }
}

// =======================================================================
// launch
// =======================================================================
extern "C" void kernel_launch(void* const* d_in, const int* in_sizes, int n_in,
                              void* d_out, int out_size) {
    const void* x   = nullptr;
    const void* qw  = nullptr;
    const void* wsc = nullptr;
    const void* smo = nullptr;
    const void* pd  = nullptr;
    const void* pu  = nullptr;

    for (int i = 0; i < n_in; ++i) {
        switch (in_sizes[i]) {
            case 33554432: x   = d_in[i]; break;
            case 16777216: qw  = d_in[i]; break;
            case 262144:   wsc = d_in[i]; break;
            case 4096:     smo = d_in[i]; break;
            case 131072:   if (!pd) pd = d_in[i]; else pu = d_in[i]; break;
            default: break;
        }
    }
    if (!x || !qw || !wsc || !smo || !pd || !pu) {
        x   = d_in[0];
        qw  = d_in[1];
        wsc = d_in[2];
        smo = d_in[3];
        pd  = d_in[4];
        pu  = d_in[5];
    }

    float* out = (float*)d_out;

    cudaFuncSetAttribute(gemm_main_kernel,
                         cudaFuncAttributeMaxDynamicSharedMemorySize, SMEM_BYTES);

    detect_qw_kernel<<<1, 32>>>((const int*)qw);
    prep_x_kernel<<<M_TOK, 256>>>((const float*)x, (const float*)smo);
    prep_w_kernel<<<OUT_F, 256>>>(qw, (const float*)wsc, (const float*)pu);
    lora_part_kernel<<<dim3(M_TOK / 64, 4), 256>>>((const float*)pd);
    lora_pack_kernel<<<M_TOK * RANK / 256, 256>>>();
    gemm_main_kernel<<<dim3(OUT_F / B_ROWS, M_TOK / A_ROWS), 256, SMEM_BYTES>>>(out);
}

// round 12
// speedup vs baseline: 1.3617x; 1.1642x over previous
#include <cuda_runtime.h>
#include <cuda_fp16.h>
#include <cstdint>
#include <cstddef>

// ---------------- problem constants ----------------
#define M_TOK 8192
#define IN_F  4096
#define OUT_F 4096
#define RANK  32
#define GS    64
#define KP    4160          // IN_F + RANK (lora) + 32 (zero pad); multiple of 64
#define KT_MAIN (KP / 64)   // 65 K-tiles of 64

// ---------------- scratch (device globals; no runtime allocation) ----------------
__device__ __align__(128) __half g_A [(size_t)M_TOK * KP];   // A' = [xdq | lora_act | 0]
__device__ __align__(128) __half g_B [(size_t)OUT_F * KP];   // B' = [wdq | proj_up  | 0]
__device__ __align__(128) __half g_Xs[(size_t)M_TOK * IN_F]; // smoothed activations (half)

// ---------------- common helpers ----------------
__device__ __forceinline__ uint32_t smem_u32(const void* p) {
    uint32_t a;
    asm("{ .reg .u64 t; cvta.to.shared.u64 t, %1; cvt.u32.u64 %0, t; }" : "=r"(a) : "l"(p));
    return a;
}
__device__ __forceinline__ void cp16s(uint32_t sdst, const void* gsrc) {
    asm volatile("cp.async.cg.shared.global [%0], [%1], 16;\n" :: "r"(sdst), "l"(gsrc));
}
#define LDSM_X4(r0, r1, r2, r3, a)                                             \
    asm volatile("ldmatrix.sync.aligned.m8n8.x4.shared.b16 {%0,%1,%2,%3}, [%4];" \
                 : "=r"(r0), "=r"(r1), "=r"(r2), "=r"(r3) : "r"(a))
#define MMA_16816(C, A0, A1, A2, A3, B0, B1)                                   \
    asm volatile("mma.sync.aligned.m16n8k16.row.col.f32.f16.f16.f32 "          \
                 "{%0,%1,%2,%3}, {%4,%5,%6,%7}, {%8,%9}, {%0,%1,%2,%3};\n"     \
                 : "+f"((C)[0]), "+f"((C)[1]), "+f"((C)[2]), "+f"((C)[3])      \
                 : "r"(A0), "r"(A1), "r"(A2), "r"(A3), "r"(B0), "r"(B1))

// =======================================================================
// Kernel 1: activation prep (smooth, quantize-dequantize, store A' cols 0..4095,
// zero pad cols 4128..4159, write half(xs) to g_Xs)
// =======================================================================
__global__ void __launch_bounds__(256) prep_x_kernel(const float* __restrict__ x,
                                                     const float* __restrict__ smooth) {
    const int m = blockIdx.x;
    const int t = threadIdx.x;
    const int i0 = t * 16;

    float v[16];
    const float4* xp = (const float4*)(x + (size_t)m * IN_F + i0);
    const float4* sp = (const float4*)(smooth + i0);
#pragma unroll
    for (int j = 0; j < 4; ++j) {
        float4 xv = xp[j];
        float4 sv = sp[j];
        v[4*j+0] = xv.x / sv.x;
        v[4*j+1] = xv.y / sv.y;
        v[4*j+2] = xv.z / sv.z;
        v[4*j+3] = xv.w / sv.w;
    }

    __align__(16) __half hs[16];
#pragma unroll
    for (int j = 0; j < 16; ++j) hs[j] = __float2half_rn(v[j]);
    {
        uint4* dst = (uint4*)(g_Xs + (size_t)m * IN_F + i0);
        dst[0] = ((const uint4*)hs)[0];
        dst[1] = ((const uint4*)hs)[1];
    }

    float am = 0.f;
#pragma unroll
    for (int j = 0; j < 16; ++j) am = fmaxf(am, fabsf(v[j]));
    am = fmaxf(am, __shfl_xor_sync(0xffffffffu, am, 1));
    am = fmaxf(am, __shfl_xor_sync(0xffffffffu, am, 2));
    const float asc = fmaxf(am / 7.0f, 1e-8f);

    __align__(16) __half hq[16];
#pragma unroll
    for (int j = 0; j < 16; ++j) {
        float q = rintf(v[j] / asc);            // round-half-even == jnp.round
        q = fminf(fmaxf(q, -8.0f), 7.0f);
        hq[j] = __float2half_rn(q * asc);
    }
    {
        uint4* dst = (uint4*)(g_A + (size_t)m * KP + i0);
        dst[0] = ((const uint4*)hq)[0];
        dst[1] = ((const uint4*)hq)[1];
    }

    if (t < 4) {
        uint4 z = make_uint4(0u, 0u, 0u, 0u);
        *(uint4*)(g_A + (size_t)m * KP + (IN_F + RANK) + t * 8) = z;
    }
}

// =======================================================================
// Kernel 2: weight prep. Per-block inline dtype detect: if first 64 dwords of
// the qweight buffer all lie in [-8,7], the harness promoted int8 -> int32
// (P[false positive] ~ 2^-23 per dword). Uniform branch; loads L2-hit.
// =======================================================================
__global__ void __launch_bounds__(256) prep_w_kernel(const void* __restrict__ qw_raw,
                                                     const float* __restrict__ wsc,
                                                     const float* __restrict__ pu) {
    const int o = blockIdx.x;
    const int t = threadIdx.x;
    const int i0 = t * 16;

    int is_i32 = 1;
    {
        const int* qd = (const int*)qw_raw;
        for (int i = 0; i < 64; ++i) {
            int vq = qd[i];
            if (vq < -8 || vq > 7) { is_i32 = 0; break; }
        }
    }

    float qv[16];
    if (is_i32) {
        const int4* qp = (const int4*)((const int*)qw_raw + (size_t)o * IN_F + i0);
#pragma unroll
        for (int j = 0; j < 4; ++j) {
            int4 w = qp[j];
            qv[4*j+0] = (float)w.x;
            qv[4*j+1] = (float)w.y;
            qv[4*j+2] = (float)w.z;
            qv[4*j+3] = (float)w.w;
        }
    } else {
        __align__(16) int8_t qb[16];
        *(uint4*)qb = *(const uint4*)((const int8_t*)qw_raw + (size_t)o * IN_F + i0);
#pragma unroll
        for (int j = 0; j < 16; ++j) qv[j] = (float)qb[j];
    }

    const float ws = wsc[(i0 >> 6) * OUT_F + o];
    __align__(16) __half h[16];
#pragma unroll
    for (int j = 0; j < 16; ++j) h[j] = __float2half_rn(qv[j] * ws);
    {
        uint4* dst = (uint4*)(g_B + (size_t)o * KP + i0);
        dst[0] = ((const uint4*)h)[0];
        dst[1] = ((const uint4*)h)[1];
    }

    if (t < RANK) {
        g_B[(size_t)o * KP + IN_F + t] = __float2half_rn(pu[(size_t)o * RANK + t]);
    } else if (t < RANK + 32) {
        g_B[(size_t)o * KP + IN_F + RANK + (t - RANK)] = __float2half_rn(0.0f);
    }
}

// =======================================================================
// Kernel 3: lora_down via mma.sync.  lora[m,r] = sum_k Xs[m,k] * pd[k,r]
// Writes half result directly into g_A[:, 4096:4128].
// Block: 128 token rows, 8 warps x 16 rows, N=32, K chunks of 64,
// 3-stage cp.async ring. pd transposed f32->half into smem [n][k] layout.
// =======================================================================
#define LSA 72
#define L_XS_ROWS 128
#define L_PD_OFF  128                          // pd rows 128..159 within stage
#define L_STAGE_H ((L_XS_ROWS + RANK) * LSA)   // 11520 halfs per stage
#define L_SMEM_BYTES (3 * L_STAGE_H * 2)       // 69120 bytes
#define L_KC (IN_F / 64)                       // 64 chunks

__device__ __forceinline__ void lora_load_stage(uint32_t sbase, int slot, int kc,
                                                int m0, const float* __restrict__ pd,
                                                int t) {
    uint32_t st = sbase + slot * (L_STAGE_H * 2);
    // Xs tile: 128 rows x 128 B, 1024 chunks / 256 threads
    const __half* gX = g_Xs + (size_t)m0 * IN_F + kc * 64;
#pragma unroll
    for (int j = 0; j < 4; ++j) {
        int c = j * 256 + t;
        int row = c >> 3, cc = c & 7;
        cp16s(st + (row * LSA + cc * 8) * 2, gX + (size_t)row * IN_F + cc * 8);
    }
    // pd chunk 64(k) x 32(r) f32 -> transposed half smem [r][k]
    int k = t >> 2;                      // 0..63
    int rg = (t & 3) * 8;                // 0,8,16,24
    const float* prow = pd + (size_t)(kc * 64 + k) * RANK + rg;
    float4 p0 = *(const float4*)(prow);
    float4 p1 = *(const float4*)(prow + 4);
    __half hv[8];
    hv[0] = __float2half_rn(p0.x); hv[1] = __float2half_rn(p0.y);
    hv[2] = __float2half_rn(p0.z); hv[3] = __float2half_rn(p0.w);
    hv[4] = __float2half_rn(p1.x); hv[5] = __float2half_rn(p1.y);
    hv[6] = __float2half_rn(p1.z); hv[7] = __float2half_rn(p1.w);
#pragma unroll
    for (int i = 0; i < 8; ++i) {
        uint32_t addr = st + ((L_PD_OFF + rg + i) * LSA + k) * 2;
        asm volatile("st.shared.b16 [%0], %1;" :: "r"(addr),
                     "h"(*(const uint16_t*)&hv[i]) : "memory");
    }
}

__global__ void __launch_bounds__(256, 1) lora_down_kernel(const float* __restrict__ pd) {
    extern __shared__ __align__(128) __half lsmem[];
    uint32_t sbase = smem_u32(lsmem);

    const int t = threadIdx.x;
    const int wid = t >> 5, lane = t & 31;
    const int gid = lane >> 2, tid4 = lane & 3;
    const int m0 = blockIdx.x * L_XS_ROWS;

    const int a_r = (lane & 15);
    const int a_k = (lane >> 4) * 8;
    const int b_r = ((lane >> 4) << 3) + (lane & 7);
    const int b_k = ((lane >> 3) & 1) * 8;

    float c[4][4];
#pragma unroll
    for (int ni = 0; ni < 4; ++ni)
#pragma unroll
        for (int j = 0; j < 4; ++j) c[ni][j] = 0.f;

    lora_load_stage(sbase, 0, 0, m0, pd, t);
    asm volatile("cp.async.commit_group;\n");
    lora_load_stage(sbase, 1, 1, m0, pd, t);
    asm volatile("cp.async.commit_group;\n");

    int s = 0;
    for (int kc = 0; kc < L_KC; ++kc) {
        asm volatile("cp.async.wait_group 1;\n");
        __syncthreads();

        if (kc + 2 < L_KC) {
            int s2 = kc + 2;
            s2 -= (s2 / 3) * 3;
            lora_load_stage(sbase, s2, kc + 2, m0, pd, t);
        }
        asm volatile("cp.async.commit_group;\n");

        uint32_t st = sbase + s * (L_STAGE_H * 2);
#pragma unroll
        for (int ks = 0; ks < 4; ++ks) {
            uint32_t af[4], bf[4][2];
            {
                uint32_t addr = st + ((wid * 16 + a_r) * LSA + ks * 16 + a_k) * 2;
                LDSM_X4(af[0], af[1], af[2], af[3], addr);
            }
#pragma unroll
            for (int np = 0; np < 2; ++np) {
                uint32_t addr = st + ((L_PD_OFF + np * 16 + b_r) * LSA + ks * 16 + b_k) * 2;
                LDSM_X4(bf[2*np][0], bf[2*np][1], bf[2*np+1][0], bf[2*np+1][1], addr);
            }
#pragma unroll
            for (int ni = 0; ni < 4; ++ni)
                MMA_16816(c[ni], af[0], af[1], af[2], af[3], bf[ni][0], bf[ni][1]);
        }
        ++s;
        if (s == 3) s = 0;
    }

    // write half(lora) into g_A cols 4096..4127
#pragma unroll
    for (int ni = 0; ni < 4; ++ni) {
        int row = m0 + wid * 16 + gid;
        int col = IN_F + ni * 8 + tid4 * 2;
        __half2 v0 = __floats2half2_rn(c[ni][0], c[ni][1]);
        __half2 v1 = __floats2half2_rn(c[ni][2], c[ni][3]);
        *(__half2*)(g_A + (size_t)row * KP + col) = v0;
        *(__half2*)(g_A + (size_t)(row + 8) * KP + col) = v1;
    }
}

// =======================================================================
// Kernel 4: main GEMM, mma.sync + ldmatrix (unchanged from R10 pass).
// BM=256, BN=128, BK=64. 256 threads = 8 warps (wm 0..3, wn 0..1),
// warp tile 64x64 -> 4x8 m16n8k16 frags. 3-stage cp.async. SA=72 stride.
// =======================================================================
#define SA 72
#define A_ROWS 256
#define B_ROWS 128
#define STAGE_H ((A_ROWS + B_ROWS) * SA)
#define B_OFF_H (A_ROWS * SA)
#define SMEM_BYTES (3 * STAGE_H * 2)              // 165888 bytes

__device__ __forceinline__ void load_stage(uint32_t sbase, int slot, int kt,
                                           int m0, int n0, int t) {
    uint32_t st = sbase + slot * (STAGE_H * 2);
    const __half* gA = g_A + (size_t)m0 * KP + kt * 64;
    const __half* gB = g_B + (size_t)n0 * KP + kt * 64;
#pragma unroll
    for (int j = 0; j < 12; ++j) {
        int c = j * 256 + t;
        int row = c >> 3, cc = c & 7;
        if (row < A_ROWS) {
            cp16s(st + (row * SA + cc * 8) * 2, gA + (size_t)row * KP + cc * 8);
        } else {
            int br = row - A_ROWS;
            cp16s(st + (B_OFF_H + br * SA + cc * 8) * 2, gB + (size_t)br * KP + cc * 8);
        }
    }
}

__global__ void __launch_bounds__(256, 1) gemm_main_kernel(float* __restrict__ out) {
    extern __shared__ __align__(128) __half smem[];
    uint32_t sbase = smem_u32(smem);

    const int t = threadIdx.x;
    const int wid = t >> 5, lane = t & 31;
    const int wm = wid >> 1, wn = wid & 1;
    const int gid = lane >> 2, tid4 = lane & 3;
    const int n0 = blockIdx.x * B_ROWS;
    const int m0 = blockIdx.y * A_ROWS;

    const int a_r = (lane & 15);
    const int a_k = (lane >> 4) * 8;
    const int b_r = ((lane >> 4) << 3) + (lane & 7);
    const int b_k = ((lane >> 3) & 1) * 8;

    float c[4][8][4];
#pragma unroll
    for (int mi = 0; mi < 4; ++mi)
#pragma unroll
        for (int ni = 0; ni < 8; ++ni)
#pragma unroll
            for (int j = 0; j < 4; ++j) c[mi][ni][j] = 0.f;

    load_stage(sbase, 0, 0, m0, n0, t);
    asm volatile("cp.async.commit_group;\n");
    load_stage(sbase, 1, 1, m0, n0, t);
    asm volatile("cp.async.commit_group;\n");

    int s = 0;
    for (int kt = 0; kt < KT_MAIN; ++kt) {
        asm volatile("cp.async.wait_group 1;\n");
        __syncthreads();

        if (kt + 2 < KT_MAIN) {
            int s2 = kt + 2;
            s2 -= (s2 / 3) * 3;
            load_stage(sbase, s2, kt + 2, m0, n0, t);
        }
        asm volatile("cp.async.commit_group;\n");

        uint32_t aS = sbase + s * (STAGE_H * 2);
        uint32_t bS = aS + B_OFF_H * 2;
#pragma unroll
        for (int ks = 0; ks < 4; ++ks) {
            uint32_t af[4][4], bf[8][2];
#pragma unroll
            for (int mi = 0; mi < 4; ++mi) {
                uint32_t addr = aS + ((wm * 64 + mi * 16 + a_r) * SA + ks * 16 + a_k) * 2;
                LDSM_X4(af[mi][0], af[mi][1], af[mi][2], af[mi][3], addr);
            }
#pragma unroll
            for (int np = 0; np < 4; ++np) {
                uint32_t addr = bS + ((wn * 64 + np * 16 + b_r) * SA + ks * 16 + b_k) * 2;
                LDSM_X4(bf[2*np][0], bf[2*np][1], bf[2*np+1][0], bf[2*np+1][1], addr);
            }
#pragma unroll
            for (int mi = 0; mi < 4; ++mi)
#pragma unroll
                for (int ni = 0; ni < 8; ++ni)
                    MMA_16816(c[mi][ni], af[mi][0], af[mi][1], af[mi][2], af[mi][3],
                              bf[ni][0], bf[ni][1]);
        }
        ++s;
        if (s == 3) s = 0;
    }

#pragma unroll
    for (int mi = 0; mi < 4; ++mi) {
#pragma unroll
        for (int ni = 0; ni < 8; ++ni) {
            int row = m0 + wm * 64 + mi * 16 + gid;
            int col = n0 + wn * 64 + ni * 8 + tid4 * 2;
            *(float2*)(out + (size_t)row * OUT_F + col) =
                make_float2(c[mi][ni][0], c[mi][ni][1]);
            *(float2*)(out + (size_t)(row + 8) * OUT_F + col) =
                make_float2(c[mi][ni][2], c[mi][ni][3]);
        }
    }
}

// =======================================================================
// launch: prep_x, prep_w, lora_down, gemm (gemm = 4th launch -> ncu slot)
// =======================================================================
extern "C" void kernel_launch(void* const* d_in, const int* in_sizes, int n_in,
                              void* d_out, int out_size) {
    const void* x   = nullptr;
    const void* qw  = nullptr;
    const void* wsc = nullptr;
    const void* smo = nullptr;
    const void* pd  = nullptr;
    const void* pu  = nullptr;

    for (int i = 0; i < n_in; ++i) {
        switch (in_sizes[i]) {
            case 33554432: x   = d_in[i]; break;
            case 16777216: qw  = d_in[i]; break;
            case 262144:   wsc = d_in[i]; break;
            case 4096:     smo = d_in[i]; break;
            case 131072:   if (!pd) pd = d_in[i]; else pu = d_in[i]; break;
            default: break;
        }
    }
    if (!x || !qw || !wsc || !smo || !pd || !pu) {
        x   = d_in[0];
        qw  = d_in[1];
        wsc = d_in[2];
        smo = d_in[3];
        pd  = d_in[4];
        pu  = d_in[5];
    }

    float* out = (float*)d_out;

    cudaFuncSetAttribute(gemm_main_kernel,
                         cudaFuncAttributeMaxDynamicSharedMemorySize, SMEM_BYTES);
    cudaFuncSetAttribute(lora_down_kernel,
                         cudaFuncAttributeMaxDynamicSharedMemorySize, L_SMEM_BYTES);

    prep_x_kernel<<<M_TOK, 256>>>((const float*)x, (const float*)smo);
    prep_w_kernel<<<OUT_F, 256>>>(qw, (const float*)wsc, (const float*)pu);
    lora_down_kernel<<<M_TOK / 128, 256, L_SMEM_BYTES>>>((const float*)pd);
    gemm_main_kernel<<<dim3(OUT_F / B_ROWS, M_TOK / A_ROWS), 256, SMEM_BYTES>>>(out);
}

// round 14
// speedup vs baseline: 1.3619x; 1.0002x over previous
#include <cuda_runtime.h>
#include <cuda_fp16.h>
#include <cstdint>
#include <cstddef>

// ---------------- problem constants ----------------
#define M_TOK 8192
#define IN_F  4096
#define OUT_F 4096
#define RANK  32
#define GS    64
#define KP    4160          // IN_F + RANK (lora) + 32 (zero pad); multiple of 64
#define KT_MAIN (KP / 64)   // 65 K-tiles of 64

// ---------------- scratch (device globals; no runtime allocation) ----------------
__device__ __align__(128) __half g_A [(size_t)M_TOK * KP];   // A' = [xdq | lora_act | 0]
__device__ __align__(128) __half g_B [(size_t)OUT_F * KP];   // B' = [wdq | proj_up  | 0]
__device__ __align__(128) __half g_Xs[(size_t)M_TOK * IN_F]; // smoothed activations (half)

// ---------------- common helpers ----------------
__device__ __forceinline__ uint32_t smem_u32(const void* p) {
    uint32_t a;
    asm("{ .reg .u64 t; cvta.to.shared.u64 t, %1; cvt.u32.u64 %0, t; }" : "=r"(a) : "l"(p));
    return a;
}
__device__ __forceinline__ void cp16s(uint32_t sdst, const void* gsrc) {
    asm volatile("cp.async.cg.shared.global [%0], [%1], 16;\n" :: "r"(sdst), "l"(gsrc));
}
#define LDSM_X4(r0, r1, r2, r3, a)                                             \
    asm volatile("ldmatrix.sync.aligned.m8n8.x4.shared.b16 {%0,%1,%2,%3}, [%4];" \
                 : "=r"(r0), "=r"(r1), "=r"(r2), "=r"(r3) : "r"(a))
#define MMA_16816(C, A0, A1, A2, A3, B0, B1)                                   \
    asm volatile("mma.sync.aligned.m16n8k16.row.col.f32.f16.f16.f32 "          \
                 "{%0,%1,%2,%3}, {%4,%5,%6,%7}, {%8,%9}, {%0,%1,%2,%3};\n"     \
                 : "+f"((C)[0]), "+f"((C)[1]), "+f"((C)[2]), "+f"((C)[3])      \
                 : "r"(A0), "r"(A1), "r"(A2), "r"(A3), "r"(B0), "r"(B1))

// =======================================================================
// Kernel 1: activation prep (smooth, quantize-dequantize, store A' cols 0..4095,
// zero pad cols 4128..4159, write half(xs) to g_Xs)
// =======================================================================
__global__ void __launch_bounds__(256) prep_x_kernel(const float* __restrict__ x,
                                                     const float* __restrict__ smooth) {
    const int m = blockIdx.x;
    const int t = threadIdx.x;
    const int i0 = t * 16;

    float v[16];
    const float4* xp = (const float4*)(x + (size_t)m * IN_F + i0);
    const float4* sp = (const float4*)(smooth + i0);
#pragma unroll
    for (int j = 0; j < 4; ++j) {
        float4 xv = xp[j];
        float4 sv = sp[j];
        v[4*j+0] = xv.x / sv.x;
        v[4*j+1] = xv.y / sv.y;
        v[4*j+2] = xv.z / sv.z;
        v[4*j+3] = xv.w / sv.w;
    }

    __align__(16) __half hs[16];
#pragma unroll
    for (int j = 0; j < 16; ++j) hs[j] = __float2half_rn(v[j]);
    {
        uint4* dst = (uint4*)(g_Xs + (size_t)m * IN_F + i0);
        dst[0] = ((const uint4*)hs)[0];
        dst[1] = ((const uint4*)hs)[1];
    }

    float am = 0.f;
#pragma unroll
    for (int j = 0; j < 16; ++j) am = fmaxf(am, fabsf(v[j]));
    am = fmaxf(am, __shfl_xor_sync(0xffffffffu, am, 1));
    am = fmaxf(am, __shfl_xor_sync(0xffffffffu, am, 2));
    const float asc = fmaxf(am / 7.0f, 1e-8f);

    __align__(16) __half hq[16];
#pragma unroll
    for (int j = 0; j < 16; ++j) {
        float q = rintf(v[j] / asc);            // round-half-even == jnp.round
        q = fminf(fmaxf(q, -8.0f), 7.0f);
        hq[j] = __float2half_rn(q * asc);
    }
    {
        uint4* dst = (uint4*)(g_A + (size_t)m * KP + i0);
        dst[0] = ((const uint4*)hq)[0];
        dst[1] = ((const uint4*)hq)[1];
    }

    if (t < 4) {
        uint4 z = make_uint4(0u, 0u, 0u, 0u);
        *(uint4*)(g_A + (size_t)m * KP + (IN_F + RANK) + t * 8) = z;
    }
}

// =======================================================================
// Kernel 2: weight prep. Per-block inline dtype detect: if first 64 dwords of
// the qweight buffer all lie in [-8,7], the harness promoted int8 -> int32.
// =======================================================================
__global__ void __launch_bounds__(256) prep_w_kernel(const void* __restrict__ qw_raw,
                                                     const float* __restrict__ wsc,
                                                     const float* __restrict__ pu) {
    const int o = blockIdx.x;
    const int t = threadIdx.x;
    const int i0 = t * 16;

    int is_i32 = 1;
    {
        const int* qd = (const int*)qw_raw;
        for (int i = 0; i < 64; ++i) {
            int vq = qd[i];
            if (vq < -8 || vq > 7) { is_i32 = 0; break; }
        }
    }

    float qv[16];
    if (is_i32) {
        const int4* qp = (const int4*)((const int*)qw_raw + (size_t)o * IN_F + i0);
#pragma unroll
        for (int j = 0; j < 4; ++j) {
            int4 w = qp[j];
            qv[4*j+0] = (float)w.x;
            qv[4*j+1] = (float)w.y;
            qv[4*j+2] = (float)w.z;
            qv[4*j+3] = (float)w.w;
        }
    } else {
        __align__(16) int8_t qb[16];
        *(uint4*)qb = *(const uint4*)((const int8_t*)qw_raw + (size_t)o * IN_F + i0);
#pragma unroll
        for (int j = 0; j < 16; ++j) qv[j] = (float)qb[j];
    }

    const float ws = wsc[(i0 >> 6) * OUT_F + o];
    __align__(16) __half h[16];
#pragma unroll
    for (int j = 0; j < 16; ++j) h[j] = __float2half_rn(qv[j] * ws);
    {
        uint4* dst = (uint4*)(g_B + (size_t)o * KP + i0);
        dst[0] = ((const uint4*)h)[0];
        dst[1] = ((const uint4*)h)[1];
    }

    if (t < RANK) {
        g_B[(size_t)o * KP + IN_F + t] = __float2half_rn(pu[(size_t)o * RANK + t]);
    } else if (t < RANK + 32) {
        g_B[(size_t)o * KP + IN_F + RANK + (t - RANK)] = __float2half_rn(0.0f);
    }
}

// =======================================================================
// Kernel 3: lora_down via mma.sync.  lora[m,r] = sum_k Xs[m,k] * pd[k,r]
// Writes half result directly into g_A[:, 4096:4128].
// =======================================================================
#define LSA 72
#define L_XS_ROWS 128
#define L_PD_OFF  128
#define L_STAGE_H ((L_XS_ROWS + RANK) * LSA)
#define L_SMEM_BYTES (3 * L_STAGE_H * 2)       // 69120 bytes
#define L_KC (IN_F / 64)

__device__ __forceinline__ void lora_load_stage(uint32_t sbase, int slot, int kc,
                                                int m0, const float* __restrict__ pd,
                                                int t) {
    uint32_t st = sbase + slot * (L_STAGE_H * 2);
    const __half* gX = g_Xs + (size_t)m0 * IN_F + kc * 64;
#pragma unroll
    for (int j = 0; j < 4; ++j) {
        int c = j * 256 + t;
        int row = c >> 3, cc = c & 7;
        cp16s(st + (row * LSA + cc * 8) * 2, gX + (size_t)row * IN_F + cc * 8);
    }
    int k = t >> 2;
    int rg = (t & 3) * 8;
    const float* prow = pd + (size_t)(kc * 64 + k) * RANK + rg;
    float4 p0 = *(const float4*)(prow);
    float4 p1 = *(const float4*)(prow + 4);
    __half hv[8];
    hv[0] = __float2half_rn(p0.x); hv[1] = __float2half_rn(p0.y);
    hv[2] = __float2half_rn(p0.z); hv[3] = __float2half_rn(p0.w);
    hv[4] = __float2half_rn(p1.x); hv[5] = __float2half_rn(p1.y);
    hv[6] = __float2half_rn(p1.z); hv[7] = __float2half_rn(p1.w);
#pragma unroll
    for (int i = 0; i < 8; ++i) {
        uint32_t addr = st + ((L_PD_OFF + rg + i) * LSA + k) * 2;
        asm volatile("st.shared.b16 [%0], %1;" :: "r"(addr),
                     "h"(*(const uint16_t*)&hv[i]) : "memory");
    }
}

__global__ void __launch_bounds__(256, 1) lora_down_kernel(const float* __restrict__ pd) {
    extern __shared__ __align__(128) __half lsmem[];
    uint32_t sbase = smem_u32(lsmem);

    const int t = threadIdx.x;
    const int wid = t >> 5, lane = t & 31;
    const int gid = lane >> 2, tid4 = lane & 3;
    const int m0 = blockIdx.x * L_XS_ROWS;

    const int a_r = (lane & 15);
    const int a_k = (lane >> 4) * 8;
    const int b_r = ((lane >> 4) << 3) + (lane & 7);
    const int b_k = ((lane >> 3) & 1) * 8;

    float c[4][4];
#pragma unroll
    for (int ni = 0; ni < 4; ++ni)
#pragma unroll
        for (int j = 0; j < 4; ++j) c[ni][j] = 0.f;

    lora_load_stage(sbase, 0, 0, m0, pd, t);
    asm volatile("cp.async.commit_group;\n");
    lora_load_stage(sbase, 1, 1, m0, pd, t);
    asm volatile("cp.async.commit_group;\n");

    int s = 0;
    for (int kc = 0; kc < L_KC; ++kc) {
        asm volatile("cp.async.wait_group 1;\n");
        __syncthreads();

        if (kc + 2 < L_KC) {
            int s2 = kc + 2;
            s2 -= (s2 / 3) * 3;
            lora_load_stage(sbase, s2, kc + 2, m0, pd, t);
        }
        asm volatile("cp.async.commit_group;\n");

        uint32_t st = sbase + s * (L_STAGE_H * 2);
#pragma unroll
        for (int ks = 0; ks < 4; ++ks) {
            uint32_t af[4], bf[4][2];
            {
                uint32_t addr = st + ((wid * 16 + a_r) * LSA + ks * 16 + a_k) * 2;
                LDSM_X4(af[0], af[1], af[2], af[3], addr);
            }
#pragma unroll
            for (int np = 0; np < 2; ++np) {
                uint32_t addr = st + ((L_PD_OFF + np * 16 + b_r) * LSA + ks * 16 + b_k) * 2;
                LDSM_X4(bf[2*np][0], bf[2*np][1], bf[2*np+1][0], bf[2*np+1][1], addr);
            }
#pragma unroll
            for (int ni = 0; ni < 4; ++ni)
                MMA_16816(c[ni], af[0], af[1], af[2], af[3], bf[ni][0], bf[ni][1]);
        }
        ++s;
        if (s == 3) s = 0;
    }

#pragma unroll
    for (int ni = 0; ni < 4; ++ni) {
        int row = m0 + wid * 16 + gid;
        int col = IN_F + ni * 8 + tid4 * 2;
        __half2 v0 = __floats2half2_rn(c[ni][0], c[ni][1]);
        __half2 v1 = __floats2half2_rn(c[ni][2], c[ni][3]);
        *(__half2*)(g_A + (size_t)row * KP + col) = v0;
        *(__half2*)(g_A + (size_t)(row + 8) * KP + col) = v1;
    }
}

// =======================================================================
// Kernel 4: main GEMM, mma.sync + ldmatrix.
// BM=256, BN=128, BK=64. 512 threads = 16 warps (wm 0..3, wn 0..3),
// warp tile 64x32 -> 4x4 m16n8k16 frags (64 acc regs -> ~120 regs/thread,
// 16 warps/SM = 4 per SMSP for latency hiding). 3-stage cp.async. SA=72.
// =======================================================================
#define SA 72
#define A_ROWS 256
#define B_ROWS 128
#define STAGE_H ((A_ROWS + B_ROWS) * SA)
#define B_OFF_H (A_ROWS * SA)
#define SMEM_BYTES (3 * STAGE_H * 2)              // 165888 bytes
#define G_THREADS 512

__device__ __forceinline__ void load_stage(uint32_t sbase, int slot, int kt,
                                           int m0, int n0, int t) {
    uint32_t st = sbase + slot * (STAGE_H * 2);
    const __half* gA = g_A + (size_t)m0 * KP + kt * 64;
    const __half* gB = g_B + (size_t)n0 * KP + kt * 64;
#pragma unroll
    for (int j = 0; j < 6; ++j) {                 // 3072 chunks / 512 threads
        int c = j * G_THREADS + t;
        int row = c >> 3, cc = c & 7;
        if (row < A_ROWS) {
            cp16s(st + (row * SA + cc * 8) * 2, gA + (size_t)row * KP + cc * 8);
        } else {
            int br = row - A_ROWS;
            cp16s(st + (B_OFF_H + br * SA + cc * 8) * 2, gB + (size_t)br * KP + cc * 8);
        }
    }
}

__global__ void __launch_bounds__(G_THREADS, 1) gemm_main_kernel(float* __restrict__ out) {
    extern __shared__ __align__(128) __half smem[];
    uint32_t sbase = smem_u32(smem);

    const int t = threadIdx.x;
    const int wid = t >> 5, lane = t & 31;
    const int wm = wid & 3, wn = wid >> 2;        // 4 x 4 warp grid
    const int gid = lane >> 2, tid4 = lane & 3;
    const int n0 = blockIdx.x * B_ROWS;
    const int m0 = blockIdx.y * A_ROWS;

    const int a_r = (lane & 15);
    const int a_k = (lane >> 4) * 8;
    const int b_r = ((lane >> 4) << 3) + (lane & 7);
    const int b_k = ((lane >> 3) & 1) * 8;

    float c[4][4][4];
#pragma unroll
    for (int mi = 0; mi < 4; ++mi)
#pragma unroll
        for (int ni = 0; ni < 4; ++ni)
#pragma unroll
            for (int j = 0; j < 4; ++j) c[mi][ni][j] = 0.f;

    load_stage(sbase, 0, 0, m0, n0, t);
    asm volatile("cp.async.commit_group;\n");
    load_stage(sbase, 1, 1, m0, n0, t);
    asm volatile("cp.async.commit_group;\n");

    int s = 0;
    for (int kt = 0; kt < KT_MAIN; ++kt) {
        asm volatile("cp.async.wait_group 1;\n");
        __syncthreads();

        if (kt + 2 < KT_MAIN) {
            int s2 = kt + 2;
            s2 -= (s2 / 3) * 3;
            load_stage(sbase, s2, kt + 2, m0, n0, t);
        }
        asm volatile("cp.async.commit_group;\n");

        uint32_t aS = sbase + s * (STAGE_H * 2);
        uint32_t bS = aS + B_OFF_H * 2;
#pragma unroll
        for (int ks = 0; ks < 4; ++ks) {
            uint32_t af[4][4], bf[4][2];
#pragma unroll
            for (int mi = 0; mi < 4; ++mi) {
                uint32_t addr = aS + ((wm * 64 + mi * 16 + a_r) * SA + ks * 16 + a_k) * 2;
                LDSM_X4(af[mi][0], af[mi][1], af[mi][2], af[mi][3], addr);
            }
#pragma unroll
            for (int np = 0; np < 2; ++np) {      // B: 32 cols = 2 x n16
                uint32_t addr = bS + ((wn * 32 + np * 16 + b_r) * SA + ks * 16 + b_k) * 2;
                LDSM_X4(bf[2*np][0], bf[2*np][1], bf[2*np+1][0], bf[2*np+1][1], addr);
            }
#pragma unroll
            for (int mi = 0; mi < 4; ++mi)
#pragma unroll
                for (int ni = 0; ni < 4; ++ni)
                    MMA_16816(c[mi][ni], af[mi][0], af[mi][1], af[mi][2], af[mi][3],
                              bf[ni][0], bf[ni][1]);
        }
        ++s;
        if (s == 3) s = 0;
    }

#pragma unroll
    for (int mi = 0; mi < 4; ++mi) {
#pragma unroll
        for (int ni = 0; ni < 4; ++ni) {
            int row = m0 + wm * 64 + mi * 16 + gid;
            int col = n0 + wn * 32 + ni * 8 + tid4 * 2;
            *(float2*)(out + (size_t)row * OUT_F + col) =
                make_float2(c[mi][ni][0], c[mi][ni][1]);
            *(float2*)(out + (size_t)(row + 8) * OUT_F + col) =
                make_float2(c[mi][ni][2], c[mi][ni][3]);
        }
    }
}

// =======================================================================
// launch: prep_x, prep_w, lora_down, gemm (gemm = 4th launch -> ncu slot)
// =======================================================================
extern "C" void kernel_launch(void* const* d_in, const int* in_sizes, int n_in,
                              void* d_out, int out_size) {
    const void* x   = nullptr;
    const void* qw  = nullptr;
    const void* wsc = nullptr;
    const void* smo = nullptr;
    const void* pd  = nullptr;
    const void* pu  = nullptr;

    for (int i = 0; i < n_in; ++i) {
        switch (in_sizes[i]) {
            case 33554432: x   = d_in[i]; break;
            case 16777216: qw  = d_in[i]; break;
            case 262144:   wsc = d_in[i]; break;
            case 4096:     smo = d_in[i]; break;
            case 131072:   if (!pd) pd = d_in[i]; else pu = d_in[i]; break;
            default: break;
        }
    }
    if (!x || !qw || !wsc || !smo || !pd || !pu) {
        x   = d_in[0];
        qw  = d_in[1];
        wsc = d_in[2];
        smo = d_in[3];
        pd  = d_in[4];
        pu  = d_in[5];
    }

    float* out = (float*)d_out;

    cudaFuncSetAttribute(gemm_main_kernel,
                         cudaFuncAttributeMaxDynamicSharedMemorySize, SMEM_BYTES);
    cudaFuncSetAttribute(lora_down_kernel,
                         cudaFuncAttributeMaxDynamicSharedMemorySize, L_SMEM_BYTES);

    prep_x_kernel<<<M_TOK, 256>>>((const float*)x, (const float*)smo);
    prep_w_kernel<<<OUT_F, 256>>>(qw, (const float*)wsc, (const float*)pu);
    lora_down_kernel<<<M_TOK / 128, 256, L_SMEM_BYTES>>>((const float*)pd);
    gemm_main_kernel<<<dim3(OUT_F / B_ROWS, M_TOK / A_ROWS), G_THREADS, SMEM_BYTES>>>(out);
}

// round 15
// speedup vs baseline: 1.5164x; 1.1134x over previous
#include <cuda_runtime.h>
#include <cuda_fp16.h>
#include <cstdint>
#include <cstddef>

// ---------------- problem constants ----------------
#define M_TOK 8192
#define IN_F  4096
#define OUT_F 4096
#define RANK  32
#define GS    64
#define KT8   (IN_F / 64)    // 64 k-tiles of 64 (one scale group each)

// ---------------- scratch (device globals; no runtime allocation) ----------------
__device__ __align__(128) int8_t g_Aq   [(size_t)M_TOK * IN_F];   // activation int4 codes
__device__ __align__(128) int8_t g_Bq   [(size_t)OUT_F * IN_F];   // weight int4 codes
__device__ __align__(128) float  g_as   [(size_t)GS * M_TOK];     // [g][m] activation scales (64 groups)
__device__ __align__(128) __half g_Xs   [(size_t)M_TOK * IN_F];   // smoothed activations (half)
__device__ __align__(128) __half g_Alora[(size_t)M_TOK * RANK];   // lora_act (half), row stride 32
__device__ __align__(128) __half g_Bpu  [(size_t)OUT_F * RANK];   // proj_up (half), row stride 32

// ---------------- common helpers ----------------
__device__ __forceinline__ uint32_t smem_u32(const void* p) {
    uint32_t a;
    asm("{ .reg .u64 t; cvta.to.shared.u64 t, %1; cvt.u32.u64 %0, t; }" : "=r"(a) : "l"(p));
    return a;
}
__device__ __forceinline__ void cp16s(uint32_t sdst, const void* gsrc) {
    asm volatile("cp.async.cg.shared.global [%0], [%1], 16;\n" :: "r"(sdst), "l"(gsrc));
}
#define LDSM_X4(r0, r1, r2, r3, a)                                             \
    asm volatile("ldmatrix.sync.aligned.m8n8.x4.shared.b16 {%0,%1,%2,%3}, [%4];" \
                 : "=r"(r0), "=r"(r1), "=r"(r2), "=r"(r3) : "r"(a))
#define MMA_16816(C, A0, A1, A2, A3, B0, B1)                                   \
    asm volatile("mma.sync.aligned.m16n8k16.row.col.f32.f16.f16.f32 "          \
                 "{%0,%1,%2,%3}, {%4,%5,%6,%7}, {%8,%9}, {%0,%1,%2,%3};\n"     \
                 : "+f"((C)[0]), "+f"((C)[1]), "+f"((C)[2]), "+f"((C)[3])      \
                 : "r"(A0), "r"(A1), "r"(A2), "r"(A3), "r"(B0), "r"(B1))
// s8 k32 MMA, first of group: C = 0
#define MMA_S8_Z(S, A0, A1, A2, A3, B0, B1)                                    \
    asm volatile("mma.sync.aligned.m16n8k32.row.col.s32.s8.s8.s32 "            \
                 "{%0,%1,%2,%3}, {%4,%5,%6,%7}, {%8,%9}, {%10,%10,%10,%10};\n" \
                 : "=r"((S)[0]), "=r"((S)[1]), "=r"((S)[2]), "=r"((S)[3])      \
                 : "r"(A0), "r"(A1), "r"(A2), "r"(A3), "r"(B0), "r"(B1), "r"(0))
// s8 k32 MMA, accumulate into S
#define MMA_S8_A(S, A0, A1, A2, A3, B0, B1)                                    \
    asm volatile("mma.sync.aligned.m16n8k32.row.col.s32.s8.s8.s32 "            \
                 "{%0,%1,%2,%3}, {%4,%5,%6,%7}, {%8,%9}, {%0,%1,%2,%3};\n"     \
                 : "+r"((S)[0]), "+r"((S)[1]), "+r"((S)[2]), "+r"((S)[3])      \
                 : "r"(A0), "r"(A1), "r"(A2), "r"(A3), "r"(B0), "r"(B1))

// =======================================================================
// Kernel 1: activation prep.
//  xs = x / smooth; per-token per-64 group: asc = max(max|xs|/7, 1e-8);
//  q = clip(rint(xs/asc),-8,7) -> g_Aq int8; asc -> g_as[g][m];
//  half(xs) -> g_Xs (for lora_down).
// =======================================================================
__global__ void __launch_bounds__(256) prep_x_kernel(const float* __restrict__ x,
                                                     const float* __restrict__ smooth) {
    const int m = blockIdx.x;
    const int t = threadIdx.x;
    const int i0 = t * 16;

    float v[16];
    const float4* xp = (const float4*)(x + (size_t)m * IN_F + i0);
    const float4* sp = (const float4*)(smooth + i0);
#pragma unroll
    for (int j = 0; j < 4; ++j) {
        float4 xv = xp[j];
        float4 sv = sp[j];
        v[4*j+0] = xv.x / sv.x;
        v[4*j+1] = xv.y / sv.y;
        v[4*j+2] = xv.z / sv.z;
        v[4*j+3] = xv.w / sv.w;
    }

    __align__(16) __half hs[16];
#pragma unroll
    for (int j = 0; j < 16; ++j) hs[j] = __float2half_rn(v[j]);
    {
        uint4* dst = (uint4*)(g_Xs + (size_t)m * IN_F + i0);
        dst[0] = ((const uint4*)hs)[0];
        dst[1] = ((const uint4*)hs)[1];
    }

    float am = 0.f;
#pragma unroll
    for (int j = 0; j < 16; ++j) am = fmaxf(am, fabsf(v[j]));
    am = fmaxf(am, __shfl_xor_sync(0xffffffffu, am, 1));
    am = fmaxf(am, __shfl_xor_sync(0xffffffffu, am, 2));
    const float asc = fmaxf(am / 7.0f, 1e-8f);

    __align__(16) int8_t qb[16];
#pragma unroll
    for (int j = 0; j < 16; ++j) {
        float q = rintf(v[j] / asc);            // round-half-even == jnp.round
        q = fminf(fmaxf(q, -8.0f), 7.0f);
        qb[j] = (int8_t)(int)q;
    }
    *(uint4*)(g_Aq + (size_t)m * IN_F + i0) = *(const uint4*)qb;

    if ((t & 3) == 0) g_as[(size_t)(t >> 2) * M_TOK + m] = asc;   // group = i0/64
}

// =======================================================================
// Kernel 2: weight prep. qweight (int32-promoted or raw int8) -> g_Bq int8.
// proj_up -> g_Bpu half. wscales used directly by the GEMM (already [g][n]).
// =======================================================================
__global__ void __launch_bounds__(256) prep_w_kernel(const void* __restrict__ qw_raw,
                                                     const float* __restrict__ pu) {
    const int o = blockIdx.x;
    const int t = threadIdx.x;
    const int i0 = t * 16;

    int is_i32 = 1;
    {
        const int* qd = (const int*)qw_raw;
        for (int i = 0; i < 64; ++i) {
            int vq = qd[i];
            if (vq < -8 || vq > 7) { is_i32 = 0; break; }
        }
    }

    __align__(16) int8_t qb[16];
    if (is_i32) {
        const int4* qp = (const int4*)((const int*)qw_raw + (size_t)o * IN_F + i0);
#pragma unroll
        for (int j = 0; j < 4; ++j) {
            int4 w = qp[j];
            qb[4*j+0] = (int8_t)w.x;
            qb[4*j+1] = (int8_t)w.y;
            qb[4*j+2] = (int8_t)w.z;
            qb[4*j+3] = (int8_t)w.w;
        }
    } else {
        *(uint4*)qb = *(const uint4*)((const int8_t*)qw_raw + (size_t)o * IN_F + i0);
    }
    *(uint4*)(g_Bq + (size_t)o * IN_F + i0) = *(const uint4*)qb;

    if (t < RANK)
        g_Bpu[(size_t)o * RANK + t] = __float2half_rn(pu[(size_t)o * RANK + t]);
}

// =======================================================================
// Kernel 3: lora_down via mma.sync.  lora[m,r] = sum_k Xs[m,k] * pd[k,r]
// Writes half result to g_Alora [M][32].
// =======================================================================
#define LSA 72
#define L_XS_ROWS 128
#define L_PD_OFF  128
#define L_STAGE_H ((L_XS_ROWS + RANK) * LSA)
#define L_SMEM_BYTES (3 * L_STAGE_H * 2)       // 69120 bytes
#define L_KC (IN_F / 64)

__device__ __forceinline__ void lora_load_stage(uint32_t sbase, int slot, int kc,
                                                int m0, const float* __restrict__ pd,
                                                int t) {
    uint32_t st = sbase + slot * (L_STAGE_H * 2);
    const __half* gX = g_Xs + (size_t)m0 * IN_F + kc * 64;
#pragma unroll
    for (int j = 0; j < 4; ++j) {
        int c = j * 256 + t;
        int row = c >> 3, cc = c & 7;
        cp16s(st + (row * LSA + cc * 8) * 2, gX + (size_t)row * IN_F + cc * 8);
    }
    int k = t >> 2;
    int rg = (t & 3) * 8;
    const float* prow = pd + (size_t)(kc * 64 + k) * RANK + rg;
    float4 p0 = *(const float4*)(prow);
    float4 p1 = *(const float4*)(prow + 4);
    __half hv[8];
    hv[0] = __float2half_rn(p0.x); hv[1] = __float2half_rn(p0.y);
    hv[2] = __float2half_rn(p0.z); hv[3] = __float2half_rn(p0.w);
    hv[4] = __float2half_rn(p1.x); hv[5] = __float2half_rn(p1.y);
    hv[6] = __float2half_rn(p1.z); hv[7] = __float2half_rn(p1.w);
#pragma unroll
    for (int i = 0; i < 8; ++i) {
        uint32_t addr = st + ((L_PD_OFF + rg + i) * LSA + k) * 2;
        asm volatile("st.shared.b16 [%0], %1;" :: "r"(addr),
                     "h"(*(const uint16_t*)&hv[i]) : "memory");
    }
}

__global__ void __launch_bounds__(256, 1) lora_down_kernel(const float* __restrict__ pd) {
    extern __shared__ __align__(128) __half lsmem[];
    uint32_t sbase = smem_u32(lsmem);

    const int t = threadIdx.x;
    const int wid = t >> 5, lane = t & 31;
    const int gid = lane >> 2, tid4 = lane & 3;
    const int m0 = blockIdx.x * L_XS_ROWS;

    const int a_r = (lane & 15);
    const int a_k = (lane >> 4) * 8;
    const int b_r = ((lane >> 4) << 3) + (lane & 7);
    const int b_k = ((lane >> 3) & 1) * 8;

    float c[4][4];
#pragma unroll
    for (int ni = 0; ni < 4; ++ni)
#pragma unroll
        for (int j = 0; j < 4; ++j) c[ni][j] = 0.f;

    lora_load_stage(sbase, 0, 0, m0, pd, t);
    asm volatile("cp.async.commit_group;\n");
    lora_load_stage(sbase, 1, 1, m0, pd, t);
    asm volatile("cp.async.commit_group;\n");

    int s = 0;
    for (int kc = 0; kc < L_KC; ++kc) {
        asm volatile("cp.async.wait_group 1;\n");
        __syncthreads();

        if (kc + 2 < L_KC) {
            int s2 = kc + 2;
            s2 -= (s2 / 3) * 3;
            lora_load_stage(sbase, s2, kc + 2, m0, pd, t);
        }
        asm volatile("cp.async.commit_group;\n");

        uint32_t st = sbase + s * (L_STAGE_H * 2);
#pragma unroll
        for (int ks = 0; ks < 4; ++ks) {
            uint32_t af[4], bf[4][2];
            {
                uint32_t addr = st + ((wid * 16 + a_r) * LSA + ks * 16 + a_k) * 2;
                LDSM_X4(af[0], af[1], af[2], af[3], addr);
            }
#pragma unroll
            for (int np = 0; np < 2; ++np) {
                uint32_t addr = st + ((L_PD_OFF + np * 16 + b_r) * LSA + ks * 16 + b_k) * 2;
                LDSM_X4(bf[2*np][0], bf[2*np][1], bf[2*np+1][0], bf[2*np+1][1], addr);
            }
#pragma unroll
            for (int ni = 0; ni < 4; ++ni)
                MMA_16816(c[ni], af[0], af[1], af[2], af[3], bf[ni][0], bf[ni][1]);
        }
        ++s;
        if (s == 3) s = 0;
    }

#pragma unroll
    for (int ni = 0; ni < 4; ++ni) {
        int row = m0 + wid * 16 + gid;
        int col = ni * 8 + tid4 * 2;
        __half2 v0 = __floats2half2_rn(c[ni][0], c[ni][1]);
        __half2 v1 = __floats2half2_rn(c[ni][2], c[ni][3]);
        *(__half2*)(g_Alora + (size_t)row * RANK + col) = v0;
        *(__half2*)(g_Alora + (size_t)(row + 8) * RANK + col) = v1;
    }
}

// =======================================================================
// Kernel 4: int8 main GEMM + per-group f32 rescale + f16 lora epilogue.
// BM=256, BN=128, BK=64 (one scale group per kt). 512 threads = 16 warps
// (wm 0..3, wn 0..3), warp tile 64x32: 4mi x 4ni fragments.
// Per kt: 2 s8 k32 MMAs per fragment (int32, exact) then
// c += i2f(s) * (as[m,g] * ws[n,g]).  Lora added via 2 f16 MMAs at end.
// smem rows: 64B data + 16B pad (stride 80 -> conflict-free ldmatrix).
// =======================================================================
#define SB 80
#define S_B_OFF  (256 * SB)                    // 20480
#define S_AS_OFF (S_B_OFF + 128 * SB)          // 30720
#define S_WS_OFF (S_AS_OFF + 1024)             // 31744
#define STAGE_B  (S_WS_OFF + 512 - 0)          // 32256
#define G_SMEM   (3 * STAGE_B)                 // 96768
#define G_THREADS 512

__device__ __forceinline__ void load_stage8(uint32_t sbase, int slot, int kt,
                                            int m0, int n0, int t,
                                            const float* __restrict__ wsc) {
    uint32_t st = sbase + slot * STAGE_B;
    const int8_t* gA = g_Aq + (size_t)m0 * IN_F + kt * 64;
    const int8_t* gB = g_Bq + (size_t)n0 * IN_F + kt * 64;
#pragma unroll
    for (int j = 0; j < 2; ++j) {              // A: 1024 chunks of 16B
        int c = j * G_THREADS + t;
        int row = c >> 2, cc = c & 3;
        cp16s(st + row * SB + cc * 16, gA + (size_t)row * IN_F + cc * 16);
    }
    {                                          // B: 512 chunks
        int row = t >> 2, cc = t & 3;
        cp16s(st + S_B_OFF + row * SB + cc * 16, gB + (size_t)row * IN_F + cc * 16);
    }
    if (t < 64) {                              // as: 256 f32 = 64 chunks
        cp16s(st + S_AS_OFF + t * 16, g_as + (size_t)kt * M_TOK + m0 + t * 4);
    } else if (t < 96) {                       // ws: 128 f32 = 32 chunks
        int idx = t - 64;
        cp16s(st + S_WS_OFF + idx * 16, wsc + (size_t)kt * OUT_F + n0 + idx * 4);
    }
}

__global__ void __launch_bounds__(G_THREADS, 1) gemm_int8_kernel(
        float* __restrict__ out, const float* __restrict__ wsc) {
    extern __shared__ __align__(128) char gsm[];
    uint32_t sbase = smem_u32(gsm);

    const int t = threadIdx.x;
    const int wid = t >> 5, lane = t & 31;
    const int wm = wid & 3, wn = wid >> 2;        // 4 x 4 warp grid
    const int gid = lane >> 2, tid4 = lane & 3;
    const int n0 = blockIdx.x * 128;
    const int m0 = blockIdx.y * 256;

    const int a_r  = (lane & 15);                 // A ldmatrix row within 16
    const int a_c  = (lane >> 4) * 16;            // A byte-col select
    const int b_r  = ((lane >> 4) << 3) + (lane & 7);  // B row within 16
    const int b_c  = ((lane >> 3) & 1) * 16;      // B byte-col select

    float c[4][4][4];
#pragma unroll
    for (int mi = 0; mi < 4; ++mi)
#pragma unroll
        for (int ni = 0; ni < 4; ++ni)
#pragma unroll
            for (int j = 0; j < 4; ++j) c[mi][ni][j] = 0.f;

    load_stage8(sbase, 0, 0, m0, n0, t, wsc);
    asm volatile("cp.async.commit_group;\n");
    load_stage8(sbase, 1, 1, m0, n0, t, wsc);
    asm volatile("cp.async.commit_group;\n");

    int s = 0;
    for (int kt = 0; kt < KT8; ++kt) {
        asm volatile("cp.async.wait_group 1;\n");
        __syncthreads();

        if (kt + 2 < KT8) {
            int s2 = kt + 2;
            s2 -= (s2 / 3) * 3;
            load_stage8(sbase, s2, kt + 2, m0, n0, t, wsc);
        }
        asm volatile("cp.async.commit_group;\n");

        uint32_t aS = sbase + s * STAGE_B;
        uint32_t bS = aS + S_B_OFF;
        const float* asp = (const float*)(gsm + s * STAGE_B + S_AS_OFF);
        const float* wsp = (const float*)(gsm + s * STAGE_B + S_WS_OFF);

        // per-kt scales (registers)
        float wse[4], wso[4];
#pragma unroll
        for (int ni = 0; ni < 4; ++ni) {
            int col = wn * 32 + ni * 8 + tid4 * 2;
            wse[ni] = wsp[col];
            wso[ni] = wsp[col + 1];
        }

        // B fragments: both k-halves, 4 ldmatrix.x4
        uint32_t bf0[4][2], bf1[4][2];
#pragma unroll
        for (int np = 0; np < 2; ++np) {
            uint32_t addr = bS + (wn * 32 + np * 16 + b_r) * SB + b_c;
            LDSM_X4(bf0[2*np][0], bf0[2*np][1], bf0[2*np+1][0], bf0[2*np+1][1], addr);
            LDSM_X4(bf1[2*np][0], bf1[2*np][1], bf1[2*np+1][0], bf1[2*np+1][1], addr + 32);
        }

#pragma unroll
        for (int mi = 0; mi < 4; ++mi) {
            uint32_t addr = aS + (wm * 64 + mi * 16 + a_r) * SB + a_c;
            uint32_t af0[4], af1[4];
            LDSM_X4(af0[0], af0[1], af0[2], af0[3], addr);
            LDSM_X4(af1[0], af1[1], af1[2], af1[3], addr + 32);
            float asl = asp[wm * 64 + mi * 16 + gid];
            float ash = asp[wm * 64 + mi * 16 + gid + 8];
#pragma unroll
            for (int ni = 0; ni < 4; ++ni) {
                int sacc[4];
                MMA_S8_Z(sacc, af0[0], af0[1], af0[2], af0[3], bf0[ni][0], bf0[ni][1]);
                MMA_S8_A(sacc, af1[0], af1[1], af1[2], af1[3], bf1[ni][0], bf1[ni][1]);
                c[mi][ni][0] += __int2float_rn(sacc[0]) * (asl * wse[ni]);
                c[mi][ni][1] += __int2float_rn(sacc[1]) * (asl * wso[ni]);
                c[mi][ni][2] += __int2float_rn(sacc[2]) * (ash * wse[ni]);
                c[mi][ni][3] += __int2float_rn(sacc[3]) * (ash * wso[ni]);
            }
        }
        ++s;
        if (s == 3) s = 0;
    }

    // ---- lora epilogue: c += lora_act(256x32, half) @ proj_up(128x32, half)^T
    asm volatile("cp.async.wait_group 0;\n");
    __syncthreads();
    {
        uint32_t st = sbase;                      // reuse stage 0
#pragma unroll
        for (int j = 0; j < 2; ++j) {             // A-lora: 1024 chunks (256 rows x 64B)
            int cth = j * G_THREADS + t;
            int row = cth >> 2, cc = cth & 3;
            cp16s(st + row * SB + cc * 16,
                  (const char*)g_Alora + (size_t)(m0 + row) * 64 + cc * 16);
        }
        {                                         // B-pu: 512 chunks
            int row = t >> 2, cc = t & 3;
            cp16s(st + S_B_OFF + row * SB + cc * 16,
                  (const char*)g_Bpu + (size_t)(n0 + row) * 64 + cc * 16);
        }
        asm volatile("cp.async.commit_group;\n");
        asm volatile("cp.async.wait_group 0;\n");
        __syncthreads();

#pragma unroll
        for (int ks = 0; ks < 2; ++ks) {          // k = 32 halfs = 2 x k16
            uint32_t bf[4][2];
#pragma unroll
            for (int np = 0; np < 2; ++np) {
                uint32_t addr = st + S_B_OFF + (wn * 32 + np * 16 + b_r) * SB + ks * 32 + b_c;
                LDSM_X4(bf[2*np][0], bf[2*np][1], bf[2*np+1][0], bf[2*np+1][1], addr);
            }
#pragma unroll
            for (int mi = 0; mi < 4; ++mi) {
                uint32_t addr = st + (wm * 64 + mi * 16 + a_r) * SB + ks * 32 + a_c;
                uint32_t af[4];
                LDSM_X4(af[0], af[1], af[2], af[3], addr);
#pragma unroll
                for (int ni = 0; ni < 4; ++ni)
                    MMA_16816(c[mi][ni], af[0], af[1], af[2], af[3],
                              bf[ni][0], bf[ni][1]);
            }
        }
    }

    // ---- store
#pragma unroll
    for (int mi = 0; mi < 4; ++mi) {
#pragma unroll
        for (int ni = 0; ni < 4; ++ni) {
            int row = m0 + wm * 64 + mi * 16 + gid;
            int col = n0 + wn * 32 + ni * 8 + tid4 * 2;
            *(float2*)(out + (size_t)row * OUT_F + col) =
                make_float2(c[mi][ni][0], c[mi][ni][1]);
            *(float2*)(out + (size_t)(row + 8) * OUT_F + col) =
                make_float2(c[mi][ni][2], c[mi][ni][3]);
        }
    }
}

// =======================================================================
// launch: prep_x, prep_w, lora_down, gemm (gemm = 4th launch -> ncu slot)
// =======================================================================
extern "C" void kernel_launch(void* const* d_in, const int* in_sizes, int n_in,
                              void* d_out, int out_size) {
    const void* x   = nullptr;
    const void* qw  = nullptr;
    const void* wsc = nullptr;
    const void* smo = nullptr;
    const void* pd  = nullptr;
    const void* pu  = nullptr;

    for (int i = 0; i < n_in; ++i) {
        switch (in_sizes[i]) {
            case 33554432: x   = d_in[i]; break;
            case 16777216: qw  = d_in[i]; break;
            case 262144:   wsc = d_in[i]; break;
            case 4096:     smo = d_in[i]; break;
            case 131072:   if (!pd) pd = d_in[i]; else pu = d_in[i]; break;
            default: break;
        }
    }
    if (!x || !qw || !wsc || !smo || !pd || !pu) {
        x   = d_in[0];
        qw  = d_in[1];
        wsc = d_in[2];
        smo = d_in[3];
        pd  = d_in[4];
        pu  = d_in[5];
    }

    float* out = (float*)d_out;

    cudaFuncSetAttribute(gemm_int8_kernel,
                         cudaFuncAttributeMaxDynamicSharedMemorySize, G_SMEM);
    cudaFuncSetAttribute(lora_down_kernel,
                         cudaFuncAttributeMaxDynamicSharedMemorySize, L_SMEM_BYTES);

    prep_x_kernel<<<M_TOK, 256>>>((const float*)x, (const float*)smo);
    prep_w_kernel<<<OUT_F, 256>>>(qw, (const float*)pu);
    lora_down_kernel<<<M_TOK / 128, 256, L_SMEM_BYTES>>>((const float*)pd);
    gemm_int8_kernel<<<dim3(OUT_F / 128, M_TOK / 256), G_THREADS, G_SMEM>>>(
        out, (const float*)wsc);
}

// round 16
// speedup vs baseline: 1.6687x; 1.1005x over previous
#include <cuda_runtime.h>
#include <cuda_fp16.h>
#include <cstdint>
#include <cstddef>

// ---------------- problem constants ----------------
#define M_TOK 8192
#define IN_F  4096
#define OUT_F 4096
#define RANK  32
#define GS    64
#define KT8   (IN_F / 64)    // 64 k-tiles of 64 (one scale group each)

// ---------------- scratch (device globals; no runtime allocation) ----------------
__device__ __align__(128) int8_t g_Aq   [(size_t)M_TOK * IN_F];   // activation int4 codes
__device__ __align__(128) int8_t g_Bq   [(size_t)OUT_F * IN_F];   // weight int4 codes
__device__ __align__(128) float  g_as   [(size_t)GS * M_TOK];     // [g][m] activation scales
__device__ __align__(128) __half g_Xs   [(size_t)M_TOK * IN_F];   // smoothed activations (half)
__device__ __align__(128) __half g_Alora[(size_t)M_TOK * RANK];   // lora_act (half)
__device__ __align__(128) __half g_Bpu  [(size_t)OUT_F * RANK];   // proj_up (half)

// ---------------- common helpers ----------------
__device__ __forceinline__ uint32_t smem_u32(const void* p) {
    uint32_t a;
    asm("{ .reg .u64 t; cvta.to.shared.u64 t, %1; cvt.u32.u64 %0, t; }" : "=r"(a) : "l"(p));
    return a;
}
__device__ __forceinline__ void cp16s(uint32_t sdst, const void* gsrc) {
    asm volatile("cp.async.cg.shared.global [%0], [%1], 16;\n" :: "r"(sdst), "l"(gsrc));
}
#define LDSM_X4(r0, r1, r2, r3, a)                                             \
    asm volatile("ldmatrix.sync.aligned.m8n8.x4.shared.b16 {%0,%1,%2,%3}, [%4];" \
                 : "=r"(r0), "=r"(r1), "=r"(r2), "=r"(r3) : "r"(a))
#define MMA_16816(C, A0, A1, A2, A3, B0, B1)                                   \
    asm volatile("mma.sync.aligned.m16n8k16.row.col.f32.f16.f16.f32 "          \
                 "{%0,%1,%2,%3}, {%4,%5,%6,%7}, {%8,%9}, {%0,%1,%2,%3};\n"     \
                 : "+f"((C)[0]), "+f"((C)[1]), "+f"((C)[2]), "+f"((C)[3])      \
                 : "r"(A0), "r"(A1), "r"(A2), "r"(A3), "r"(B0), "r"(B1))
#define MMA_S8_Z(S, A0, A1, A2, A3, B0, B1)                                    \
    asm volatile("mma.sync.aligned.m16n8k32.row.col.s32.s8.s8.s32 "            \
                 "{%0,%1,%2,%3}, {%4,%5,%6,%7}, {%8,%9}, {%10,%10,%10,%10};\n" \
                 : "=r"((S)[0]), "=r"((S)[1]), "=r"((S)[2]), "=r"((S)[3])      \
                 : "r"(A0), "r"(A1), "r"(A2), "r"(A3), "r"(B0), "r"(B1), "r"(0))
#define MMA_S8_A(S, A0, A1, A2, A3, B0, B1)                                    \
    asm volatile("mma.sync.aligned.m16n8k32.row.col.s32.s8.s8.s32 "            \
                 "{%0,%1,%2,%3}, {%4,%5,%6,%7}, {%8,%9}, {%0,%1,%2,%3};\n"     \
                 : "+r"((S)[0]), "+r"((S)[1]), "+r"((S)[2]), "+r"((S)[3])      \
                 : "r"(A0), "r"(A1), "r"(A2), "r"(A3), "r"(B0), "r"(B1))

// =======================================================================
// Kernel 1: activation prep.
// =======================================================================
__global__ void __launch_bounds__(256) prep_x_kernel(const float* __restrict__ x,
                                                     const float* __restrict__ smooth) {
    const int m = blockIdx.x;
    const int t = threadIdx.x;
    const int i0 = t * 16;

    float v[16];
    const float4* xp = (const float4*)(x + (size_t)m * IN_F + i0);
    const float4* sp = (const float4*)(smooth + i0);
#pragma unroll
    for (int j = 0; j < 4; ++j) {
        float4 xv = xp[j];
        float4 sv = sp[j];
        v[4*j+0] = xv.x / sv.x;
        v[4*j+1] = xv.y / sv.y;
        v[4*j+2] = xv.z / sv.z;
        v[4*j+3] = xv.w / sv.w;
    }

    __align__(16) __half hs[16];
#pragma unroll
    for (int j = 0; j < 16; ++j) hs[j] = __float2half_rn(v[j]);
    {
        uint4* dst = (uint4*)(g_Xs + (size_t)m * IN_F + i0);
        dst[0] = ((const uint4*)hs)[0];
        dst[1] = ((const uint4*)hs)[1];
    }

    float am = 0.f;
#pragma unroll
    for (int j = 0; j < 16; ++j) am = fmaxf(am, fabsf(v[j]));
    am = fmaxf(am, __shfl_xor_sync(0xffffffffu, am, 1));
    am = fmaxf(am, __shfl_xor_sync(0xffffffffu, am, 2));
    const float asc = fmaxf(am / 7.0f, 1e-8f);

    __align__(16) int8_t qb[16];
#pragma unroll
    for (int j = 0; j < 16; ++j) {
        float q = rintf(v[j] / asc);            // round-half-even == jnp.round
        q = fminf(fmaxf(q, -8.0f), 7.0f);
        qb[j] = (int8_t)(int)q;
    }
    *(uint4*)(g_Aq + (size_t)m * IN_F + i0) = *(const uint4*)qb;

    if ((t & 3) == 0) g_as[(size_t)(t >> 2) * M_TOK + m] = asc;   // group = i0/64
}

// =======================================================================
// Kernel 2: weight prep (int32-promoted or raw int8 qweight -> g_Bq; pu -> half)
// =======================================================================
__global__ void __launch_bounds__(256) prep_w_kernel(const void* __restrict__ qw_raw,
                                                     const float* __restrict__ pu) {
    const int o = blockIdx.x;
    const int t = threadIdx.x;
    const int i0 = t * 16;

    int is_i32 = 1;
    {
        const int* qd = (const int*)qw_raw;
        for (int i = 0; i < 64; ++i) {
            int vq = qd[i];
            if (vq < -8 || vq > 7) { is_i32 = 0; break; }
        }
    }

    __align__(16) int8_t qb[16];
    if (is_i32) {
        const int4* qp = (const int4*)((const int*)qw_raw + (size_t)o * IN_F + i0);
#pragma unroll
        for (int j = 0; j < 4; ++j) {
            int4 w = qp[j];
            qb[4*j+0] = (int8_t)w.x;
            qb[4*j+1] = (int8_t)w.y;
            qb[4*j+2] = (int8_t)w.z;
            qb[4*j+3] = (int8_t)w.w;
        }
    } else {
        *(uint4*)qb = *(const uint4*)((const int8_t*)qw_raw + (size_t)o * IN_F + i0);
    }
    *(uint4*)(g_Bq + (size_t)o * IN_F + i0) = *(const uint4*)qb;

    if (t < RANK)
        g_Bpu[(size_t)o * RANK + t] = __float2half_rn(pu[(size_t)o * RANK + t]);
}

// =======================================================================
// Kernel 3: lora_down via mma.sync -> g_Alora [M][32] (half)
// =======================================================================
#define LSA 72
#define L_XS_ROWS 128
#define L_PD_OFF  128
#define L_STAGE_H ((L_XS_ROWS + RANK) * LSA)
#define L_SMEM_BYTES (3 * L_STAGE_H * 2)       // 69120 bytes
#define L_KC (IN_F / 64)

__device__ __forceinline__ void lora_load_stage(uint32_t sbase, int slot, int kc,
                                                int m0, const float* __restrict__ pd,
                                                int t) {
    uint32_t st = sbase + slot * (L_STAGE_H * 2);
    const __half* gX = g_Xs + (size_t)m0 * IN_F + kc * 64;
#pragma unroll
    for (int j = 0; j < 4; ++j) {
        int c = j * 256 + t;
        int row = c >> 3, cc = c & 7;
        cp16s(st + (row * LSA + cc * 8) * 2, gX + (size_t)row * IN_F + cc * 8);
    }
    int k = t >> 2;
    int rg = (t & 3) * 8;
    const float* prow = pd + (size_t)(kc * 64 + k) * RANK + rg;
    float4 p0 = *(const float4*)(prow);
    float4 p1 = *(const float4*)(prow + 4);
    __half hv[8];
    hv[0] = __float2half_rn(p0.x); hv[1] = __float2half_rn(p0.y);
    hv[2] = __float2half_rn(p0.z); hv[3] = __float2half_rn(p0.w);
    hv[4] = __float2half_rn(p1.x); hv[5] = __float2half_rn(p1.y);
    hv[6] = __float2half_rn(p1.z); hv[7] = __float2half_rn(p1.w);
#pragma unroll
    for (int i = 0; i < 8; ++i) {
        uint32_t addr = st + ((L_PD_OFF + rg + i) * LSA + k) * 2;
        asm volatile("st.shared.b16 [%0], %1;" :: "r"(addr),
                     "h"(*(const uint16_t*)&hv[i]) : "memory");
    }
}

__global__ void __launch_bounds__(256, 1) lora_down_kernel(const float* __restrict__ pd) {
    extern __shared__ __align__(128) __half lsmem[];
    uint32_t sbase = smem_u32(lsmem);

    const int t = threadIdx.x;
    const int wid = t >> 5, lane = t & 31;
    const int gid = lane >> 2, tid4 = lane & 3;
    const int m0 = blockIdx.x * L_XS_ROWS;

    const int a_r = (lane & 15);
    const int a_k = (lane >> 4) * 8;
    const int b_r = ((lane >> 4) << 3) + (lane & 7);
    const int b_k = ((lane >> 3) & 1) * 8;

    float c[4][4];
#pragma unroll
    for (int ni = 0; ni < 4; ++ni)
#pragma unroll
        for (int j = 0; j < 4; ++j) c[ni][j] = 0.f;

    lora_load_stage(sbase, 0, 0, m0, pd, t);
    asm volatile("cp.async.commit_group;\n");
    lora_load_stage(sbase, 1, 1, m0, pd, t);
    asm volatile("cp.async.commit_group;\n");

    int s = 0;
    for (int kc = 0; kc < L_KC; ++kc) {
        asm volatile("cp.async.wait_group 1;\n");
        __syncthreads();

        if (kc + 2 < L_KC) {
            int s2 = kc + 2;
            s2 -= (s2 / 3) * 3;
            lora_load_stage(sbase, s2, kc + 2, m0, pd, t);
        }
        asm volatile("cp.async.commit_group;\n");

        uint32_t st = sbase + s * (L_STAGE_H * 2);
#pragma unroll
        for (int ks = 0; ks < 4; ++ks) {
            uint32_t af[4], bf[4][2];
            {
                uint32_t addr = st + ((wid * 16 + a_r) * LSA + ks * 16 + a_k) * 2;
                LDSM_X4(af[0], af[1], af[2], af[3], addr);
            }
#pragma unroll
            for (int np = 0; np < 2; ++np) {
                uint32_t addr = st + ((L_PD_OFF + np * 16 + b_r) * LSA + ks * 16 + b_k) * 2;
                LDSM_X4(bf[2*np][0], bf[2*np][1], bf[2*np+1][0], bf[2*np+1][1], addr);
            }
#pragma unroll
            for (int ni = 0; ni < 4; ++ni)
                MMA_16816(c[ni], af[0], af[1], af[2], af[3], bf[ni][0], bf[ni][1]);
        }
        ++s;
        if (s == 3) s = 0;
    }

#pragma unroll
    for (int ni = 0; ni < 4; ++ni) {
        int row = m0 + wid * 16 + gid;
        int col = ni * 8 + tid4 * 2;
        __half2 v0 = __floats2half2_rn(c[ni][0], c[ni][1]);
        __half2 v1 = __floats2half2_rn(c[ni][2], c[ni][3]);
        *(__half2*)(g_Alora + (size_t)row * RANK + col) = v0;
        *(__half2*)(g_Alora + (size_t)(row + 8) * RANK + col) = v1;
    }
}

// =======================================================================
// Kernel 4: int8 main GEMM + per-group f32 rescale + f16 lora epilogue.
// BM=128, BN=128, BK=64. 256 threads = 8 warps (wm 0..1 x wn 0..3),
// warp tile 64x32: 4mi x 4ni. __launch_bounds__(256,2) -> 2 CTAs/SM
// (two independent instruction streams per SMSP for latency hiding).
// smem rows: 64B data + 16B pad (stride 80).
// =======================================================================
#define SB 80
#define S_B_OFF  (128 * SB)                    // 10240
#define S_AS_OFF (S_B_OFF + 128 * SB)          // 20480
#define S_WS_OFF (S_AS_OFF + 512)              // 20992
#define STAGE_B  (S_WS_OFF + 512)              // 21504
#define G_SMEM   (3 * STAGE_B)                 // 64512 per CTA (x2 CTAs = 129KB)
#define G_THREADS 256

__device__ __forceinline__ void load_stage8(uint32_t sbase, int slot, int kt,
                                            int m0, int n0, int t,
                                            const float* __restrict__ wsc) {
    uint32_t st = sbase + slot * STAGE_B;
    const int8_t* gA = g_Aq + (size_t)m0 * IN_F + kt * 64;
    const int8_t* gB = g_Bq + (size_t)n0 * IN_F + kt * 64;
#pragma unroll
    for (int j = 0; j < 2; ++j) {              // A: 512 chunks of 16B
        int c = j * G_THREADS + t;
        int row = c >> 2, cc = c & 3;
        cp16s(st + row * SB + cc * 16, gA + (size_t)row * IN_F + cc * 16);
    }
#pragma unroll
    for (int j = 0; j < 2; ++j) {              // B: 512 chunks
        int c = j * G_THREADS + t;
        int row = c >> 2, cc = c & 3;
        cp16s(st + S_B_OFF + row * SB + cc * 16, gB + (size_t)row * IN_F + cc * 16);
    }
    if (t < 32) {                              // as: 128 f32 = 32 chunks
        cp16s(st + S_AS_OFF + t * 16, g_as + (size_t)kt * M_TOK + m0 + t * 4);
    } else if (t < 64) {                       // ws: 128 f32 = 32 chunks
        int idx = t - 32;
        cp16s(st + S_WS_OFF + idx * 16, wsc + (size_t)kt * OUT_F + n0 + idx * 4);
    }
}

__global__ void __launch_bounds__(G_THREADS, 2) gemm_int8_kernel(
        float* __restrict__ out, const float* __restrict__ wsc) {
    extern __shared__ __align__(128) char gsm[];
    uint32_t sbase = smem_u32(gsm);

    const int t = threadIdx.x;
    const int wid = t >> 5, lane = t & 31;
    const int wm = wid >> 2, wn = wid & 3;        // 2 x 4 warp grid
    const int gid = lane >> 2, tid4 = lane & 3;
    const int n0 = blockIdx.x * 128;
    const int m0 = blockIdx.y * 128;

    const int a_r  = (lane & 15);
    const int a_c  = (lane >> 4) * 16;
    const int b_r  = ((lane >> 4) << 3) + (lane & 7);
    const int b_c  = ((lane >> 3) & 1) * 16;

    float c[4][4][4];
#pragma unroll
    for (int mi = 0; mi < 4; ++mi)
#pragma unroll
        for (int ni = 0; ni < 4; ++ni)
#pragma unroll
            for (int j = 0; j < 4; ++j) c[mi][ni][j] = 0.f;

    load_stage8(sbase, 0, 0, m0, n0, t, wsc);
    asm volatile("cp.async.commit_group;\n");
    load_stage8(sbase, 1, 1, m0, n0, t, wsc);
    asm volatile("cp.async.commit_group;\n");

    int s = 0;
    for (int kt = 0; kt < KT8; ++kt) {
        asm volatile("cp.async.wait_group 1;\n");
        __syncthreads();

        if (kt + 2 < KT8) {
            int s2 = kt + 2;
            s2 -= (s2 / 3) * 3;
            load_stage8(sbase, s2, kt + 2, m0, n0, t, wsc);
        }
        asm volatile("cp.async.commit_group;\n");

        uint32_t aS = sbase + s * STAGE_B;
        uint32_t bS = aS + S_B_OFF;
        const float* asp = (const float*)(gsm + s * STAGE_B + S_AS_OFF);
        const float* wsp = (const float*)(gsm + s * STAGE_B + S_WS_OFF);

        float wse[4], wso[4];
#pragma unroll
        for (int ni = 0; ni < 4; ++ni) {
            int col = wn * 32 + ni * 8 + tid4 * 2;
            wse[ni] = wsp[col];
            wso[ni] = wsp[col + 1];
        }

        uint32_t bf0[4][2], bf1[4][2];
#pragma unroll
        for (int np = 0; np < 2; ++np) {
            uint32_t addr = bS + (wn * 32 + np * 16 + b_r) * SB + b_c;
            LDSM_X4(bf0[2*np][0], bf0[2*np][1], bf0[2*np+1][0], bf0[2*np+1][1], addr);
            LDSM_X4(bf1[2*np][0], bf1[2*np][1], bf1[2*np+1][0], bf1[2*np+1][1], addr + 32);
        }

#pragma unroll
        for (int mi = 0; mi < 4; ++mi) {
            uint32_t addr = aS + (wm * 64 + mi * 16 + a_r) * SB + a_c;
            uint32_t af0[4], af1[4];
            LDSM_X4(af0[0], af0[1], af0[2], af0[3], addr);
            LDSM_X4(af1[0], af1[1], af1[2], af1[3], addr + 32);
            float asl = asp[wm * 64 + mi * 16 + gid];
            float ash = asp[wm * 64 + mi * 16 + gid + 8];
#pragma unroll
            for (int ni = 0; ni < 4; ++ni) {
                int sacc[4];
                MMA_S8_Z(sacc, af0[0], af0[1], af0[2], af0[3], bf0[ni][0], bf0[ni][1]);
                MMA_S8_A(sacc, af1[0], af1[1], af1[2], af1[3], bf1[ni][0], bf1[ni][1]);
                c[mi][ni][0] += __int2float_rn(sacc[0]) * (asl * wse[ni]);
                c[mi][ni][1] += __int2float_rn(sacc[1]) * (asl * wso[ni]);
                c[mi][ni][2] += __int2float_rn(sacc[2]) * (ash * wse[ni]);
                c[mi][ni][3] += __int2float_rn(sacc[3]) * (ash * wso[ni]);
            }
        }
        ++s;
        if (s == 3) s = 0;
    }

    // ---- lora epilogue: c += lora_act(128x32) @ proj_up(128x32)^T  (f16 MMA)
    asm volatile("cp.async.wait_group 0;\n");
    __syncthreads();
    {
        uint32_t st = sbase;                      // reuse stage 0
#pragma unroll
        for (int j = 0; j < 2; ++j) {             // A-lora: 512 chunks (128 rows x 64B)
            int cth = j * G_THREADS + t;
            int row = cth >> 2, cc = cth & 3;
            cp16s(st + row * SB + cc * 16,
                  (const char*)g_Alora + (size_t)(m0 + row) * 64 + cc * 16);
        }
#pragma unroll
        for (int j = 0; j < 2; ++j) {             // B-pu: 512 chunks
            int cth = j * G_THREADS + t;
            int row = cth >> 2, cc = cth & 3;
            cp16s(st + S_B_OFF + row * SB + cc * 16,
                  (const char*)g_Bpu + (size_t)(n0 + row) * 64 + cc * 16);
        }
        asm volatile("cp.async.commit_group;\n");
        asm volatile("cp.async.wait_group 0;\n");
        __syncthreads();

#pragma unroll
        for (int ks = 0; ks < 2; ++ks) {          // k = 32 halfs = 2 x k16
            uint32_t bf[4][2];
#pragma unroll
            for (int np = 0; np < 2; ++np) {
                uint32_t addr = st + S_B_OFF + (wn * 32 + np * 16 + b_r) * SB + ks * 32 + b_c;
                LDSM_X4(bf[2*np][0], bf[2*np][1], bf[2*np+1][0], bf[2*np+1][1], addr);
            }
#pragma unroll
            for (int mi = 0; mi < 4; ++mi) {
                uint32_t addr = st + (wm * 64 + mi * 16 + a_r) * SB + ks * 32 + a_c;
                uint32_t af[4];
                LDSM_X4(af[0], af[1], af[2], af[3], addr);
#pragma unroll
                for (int ni = 0; ni < 4; ++ni)
                    MMA_16816(c[mi][ni], af[0], af[1], af[2], af[3],
                              bf[ni][0], bf[ni][1]);
            }
        }
    }

    // ---- store
#pragma unroll
    for (int mi = 0; mi < 4; ++mi) {
#pragma unroll
        for (int ni = 0; ni < 4; ++ni) {
            int row = m0 + wm * 64 + mi * 16 + gid;
            int col = n0 + wn * 32 + ni * 8 + tid4 * 2;
            *(float2*)(out + (size_t)row * OUT_F + col) =
                make_float2(c[mi][ni][0], c[mi][ni][1]);
            *(float2*)(out + (size_t)(row + 8) * OUT_F + col) =
                make_float2(c[mi][ni][2], c[mi][ni][3]);
        }
    }
}

// =======================================================================
// launch: prep_x, prep_w, lora_down, gemm (gemm = 4th launch -> ncu slot)
// =======================================================================
extern "C" void kernel_launch(void* const* d_in, const int* in_sizes, int n_in,
                              void* d_out, int out_size) {
    const void* x   = nullptr;
    const void* qw  = nullptr;
    const void* wsc = nullptr;
    const void* smo = nullptr;
    const void* pd  = nullptr;
    const void* pu  = nullptr;

    for (int i = 0; i < n_in; ++i) {
        switch (in_sizes[i]) {
            case 33554432: x   = d_in[i]; break;
            case 16777216: qw  = d_in[i]; break;
            case 262144:   wsc = d_in[i]; break;
            case 4096:     smo = d_in[i]; break;
            case 131072:   if (!pd) pd = d_in[i]; else pu = d_in[i]; break;
            default: break;
        }
    }
    if (!x || !qw || !wsc || !smo || !pd || !pu) {
        x   = d_in[0];
        qw  = d_in[1];
        wsc = d_in[2];
        smo = d_in[3];
        pd  = d_in[4];
        pu  = d_in[5];
    }

    float* out = (float*)d_out;

    cudaFuncSetAttribute(gemm_int8_kernel,
                         cudaFuncAttributeMaxDynamicSharedMemorySize, G_SMEM);
    cudaFuncSetAttribute(lora_down_kernel,
                         cudaFuncAttributeMaxDynamicSharedMemorySize, L_SMEM_BYTES);

    prep_x_kernel<<<M_TOK, 256>>>((const float*)x, (const float*)smo);
    prep_w_kernel<<<OUT_F, 256>>>(qw, (const float*)pu);
    lora_down_kernel<<<M_TOK / 128, 256, L_SMEM_BYTES>>>((const float*)pd);
    gemm_int8_kernel<<<dim3(OUT_F / 128, M_TOK / 128), G_THREADS, G_SMEM>>>(
        out, (const float*)wsc);
}